// round 11
// baseline (speedup 1.0000x reference)
#include <cuda_runtime.h>
#include <cuda_fp16.h>
#include <cstdint>

#define NB 4
#define NN 10000
#define NE 160000
#define NQ 256
#define ND 128
#define NM 64
#define NU 126
#define NH 128
#define NP 7
#define OUTC (NP + ND)   // 135

#define TEE 128                    // edges per edge-tile
#define NTE_B (NE / TEE)           // 1250
#define NTE_TOT (NTE_B * NB)       // 5000

#define NT_NODE_B 157              // ceil(10000/64)
#define NT_NODE_TOT (NT_NODE_B * NB)

#define NPT_B 79                   // ceil(10000/128) proj tiles per batch
#define NPT_TOT (NPT_B * NB)       // 316

#define GRID_PERS 148              // persistent grid (== #SMs, 1 CTA/SM)

// -------- scratch (static device globals: allocation-free) --------
__device__ float g_states[NB * NN * ND];                  // 20.5 MB
__device__ __align__(16) __half g_statesH[NB * NN * ND];  // 10.2 MB fp16 mirror
__device__ float g_incoming[NB * NN * NM];                // 10.2 MB
__device__ __align__(16) __half g_P1[NB * NN * NH];       // src projections
__device__ __align__(16) __half g_P2[NB * NN * NH];       // snk projections
// CSR + tile metadata
__device__ int g_count[NN];
__device__ int g_cur[NN];
__device__ int g_sortedSrc[NE];
__device__ int g_sortedSnk[NE];
__device__ int g_li[NE];               // per-edge local unique-sink index
__device__ int g_uniq[NTE_B * TEE];    // per-tile unique sink list
__device__ int g_ucnt[NTE_B];          // per-tile unique count
// device grid barrier state (zero-init; cnt self-resets, gen monotonic)
__device__ int g_gbar_cnt;
__device__ volatile int g_gbar_gen;

// ============================ helpers ============================
__device__ __forceinline__ uint32_t smem_u32(const void* p) {
    uint32_t a;
    asm("{ .reg .u64 t; cvta.to.shared.u64 t, %1; cvt.u32.u64 %0, t; }"
        : "=r"(a) : "l"(p));
    return a;
}
__device__ __forceinline__ uint32_t pack_h2(float a, float b) {
    __half2 h = __floats2half2_rn(a, b);
    return *reinterpret_cast<uint32_t*>(&h);
}
__device__ __forceinline__ float tf32f(float f) {
    uint32_t r;
    asm("cvt.rna.tf32.f32 %0, %1;" : "=r"(r) : "f"(f));
    return __uint_as_float(r);
}
__device__ __forceinline__ void mma_f16(float* c, uint32_t a0, uint32_t a1,
                                        uint32_t a2, uint32_t a3,
                                        uint32_t b0, uint32_t b1) {
    asm volatile(
        "mma.sync.aligned.m16n8k16.row.col.f32.f16.f16.f32 "
        "{%0,%1,%2,%3}, {%4,%5,%6,%7}, {%8,%9}, {%0,%1,%2,%3};"
        : "+f"(c[0]), "+f"(c[1]), "+f"(c[2]), "+f"(c[3])
        : "r"(a0), "r"(a1), "r"(a2), "r"(a3), "r"(b0), "r"(b1));
}
__device__ __forceinline__ void mma_tf32(float* c, uint32_t a0, uint32_t a1,
                                         uint32_t a2, uint32_t a3,
                                         uint32_t b0, uint32_t b1) {
    asm volatile(
        "mma.sync.aligned.m16n8k8.row.col.f32.tf32.tf32.f32 "
        "{%0,%1,%2,%3}, {%4,%5,%6,%7}, {%8,%9}, {%0,%1,%2,%3};"
        : "+f"(c[0]), "+f"(c[1]), "+f"(c[2]), "+f"(c[3])
        : "r"(a0), "r"(a1), "r"(a2), "r"(a3), "r"(b0), "r"(b1));
}
#define CP_ASYNC16(dst, src) \
    asm volatile("cp.async.cg.shared.global [%0], [%1], 16;" \
                 :: "r"(dst), "l"(src) : "memory")
#define CP_COMMIT() asm volatile("cp.async.commit_group;" ::: "memory")
#define CP_WAIT0()  asm volatile("cp.async.wait_group 0;" ::: "memory")

// all-blocks-resident grid barrier (valid: grid=148, 1 CTA/SM)
__device__ __forceinline__ void grid_barrier(int tid) {
    __syncthreads();
    if (tid == 0) {
        __threadfence();
        int gen = g_gbar_gen;
        if (atomicAdd(&g_gbar_cnt, 1) == (int)gridDim.x - 1) {
            g_gbar_cnt = 0;
            __threadfence();
            g_gbar_gen = gen + 1;
        } else {
            while (g_gbar_gen == gen) { }
        }
        __threadfence();
    }
    __syncthreads();
}

// -------- utility kernels --------
// copy + fp16 mirror + (fused) csr count zero
__global__ void copy_states_kernel(const float* __restrict__ src) {
    int i = blockIdx.x * blockDim.x + threadIdx.x;
    const int n = NB * NN * ND / 4;
    if (i < n) {
        float4 v = reinterpret_cast<const float4*>(src)[i];
        reinterpret_cast<float4*>(g_states)[i] = v;
        __half2* mh = reinterpret_cast<__half2*>(g_statesH);
        mh[2 * i]     = __floats2half2_rn(v.x, v.y);
        mh[2 * i + 1] = __floats2half2_rn(v.z, v.w);
    }
    if (i < NN) g_count[i] = 0;
}

__global__ void init_out_kernel(const float* __restrict__ poses, float* __restrict__ out) {
    int i = blockIdx.x * blockDim.x + threadIdx.x;
    const int n = NB * NQ * OUTC;
    if (i < n) {
        int r = i / OUTC, c = i - r * OUTC;
        out[i] = (c < NP) ? poses[r * NP + c] : 0.f;
    }
}

// -------- CSR build (once per launch; graph static) --------
// hist + (fused) zero_incoming: grid is exactly 625*256 = 160000 threads
__global__ void csr_hist_kernel(const int* __restrict__ esnk) {
    int i = blockIdx.x * blockDim.x + threadIdx.x;
    float4 z = make_float4(0.f, 0.f, 0.f, 0.f);
    #pragma unroll
    for (int t = 0; t < 4; t++) {
        int j = i + t * 160000;
        if (j < NB * NN * NM / 4)
            reinterpret_cast<float4*>(g_incoming)[j] = z;
    }
    if (i < NE) atomicAdd(&g_count[esnk[i]], 1);
}
__global__ void csr_scan_kernel() {
    __shared__ int part[1024];
    int t = threadIdx.x;
    int beg = t * 10;
    int end = beg + 10 < NN ? beg + 10 : NN;
    int s = 0;
    for (int i = beg; i < end; i++) s += g_count[i];
    part[t] = s;
    __syncthreads();
    for (int d = 1; d < 1024; d <<= 1) {
        int v = (t >= d) ? part[t - d] : 0;
        __syncthreads();
        part[t] += v;
        __syncthreads();
    }
    int base = (t > 0) ? part[t - 1] : 0;
    for (int i = beg; i < end; i++) {
        g_cur[i] = base;
        base += g_count[i];
    }
}
__global__ void csr_scatter_kernel(const int* __restrict__ esrc,
                                   const int* __restrict__ esnk) {
    int i = blockIdx.x * blockDim.x + threadIdx.x;
    if (i < NE) {
        int s = esnk[i];
        int p = atomicAdd(&g_cur[s], 1);
        g_sortedSrc[p] = esrc[i];
        g_sortedSnk[p] = s;
    }
}
__global__ void tile_meta_kernel() {
    __shared__ int fl[TEE];
    int t = blockIdx.x, tid = threadIdx.x;
    int e = t * TEE + tid;
    int s = g_sortedSnk[e];
    int flag = (tid == 0) || (s != g_sortedSnk[e - 1]);
    fl[tid] = flag;
    __syncthreads();
    for (int d = 1; d < TEE; d <<= 1) {
        int v = (tid >= d) ? fl[tid - d] : 0;
        __syncthreads();
        fl[tid] += v;
        __syncthreads();
    }
    int li = fl[tid] - 1;
    g_li[e] = li;
    if (flag) g_uniq[t * TEE + li] = s;
    if (tid == TEE - 1) g_ucnt[t] = fl[tid];
}

// =====================================================================
// Fused edge+proj kernel: phase 1 = projection (tid<256, R10 proj code with
// register-pressure-split accumulators), device grid barrier, phase 2 = edge.
// smem (u32): proj phase uses PW [0,16384) + PA [16384,33792) (2 bufs [128][68]).
// edge phase (after barrier) reuses from 0:
//   EW2O 0..4096, EB2O 4096..4160, SLIO 4160..4416, SSKO 4416..4672,
//   EMSO 4672..13376, GP1O 13376..30784, GP2O 30784..48192
// total = max(50176 proj, 48192 edge) = 50176 u32
// =====================================================================
#define PW 0
#define PA 16384
#define EW2O  0
#define EB2O  4096
#define SLIO  4160
#define SSKO  4416
#define EMSO  4672
#define GP1O  13376
#define GP2O  30784
#define EDGE_SMEM_BYTES (50176 * 4)   // 200704

__device__ __forceinline__ void proj_issue(uint32_t aBase, int b, int n0, int tid) {
    const __half* stH = g_statesH + (size_t)b * NN * ND;
    #pragma unroll
    for (int t = 0; t < 8; t++) {
        int idx = tid + t * 256;       // 0..2047 (tid < 256)
        int row = idx >> 4, ch = idx & 15;
        int node = n0 + row;
        if (node >= NN) node = NN - 1;   // clamp; stores are guarded
        uint32_t dst = aBase + row * 272 + ch * 16;
        CP_ASYNC16(dst, stH + (size_t)node * ND + ch * 8);
    }
}

__device__ __forceinline__ void edge_issue(
    uint32_t gp1Base, uint32_t gp2Base, uint32_t liBase, uint32_t skBase,
    int buf, int t, int b, int tid)
{
    const int eb = t * TEE;
    const char* P1 = (const char*)(g_P1 + (size_t)b * NN * NH);
    const char* P2 = (const char*)(g_P2 + (size_t)b * NN * NH);
    uint32_t g1 = gp1Base + buf * 8704 * 4;
    uint32_t g2 = gp2Base + buf * 8704 * 4;
    #pragma unroll
    for (int i = 0; i < 4; i++) {
        int idx = tid + i * 512;        // 0..2047
        int row = idx >> 4, ch = idx & 15;
        int node = g_sortedSrc[eb + row];
        CP_ASYNC16(g1 + (uint32_t)(row * 272 + ch * 16),
                   P1 + (size_t)node * 256 + ch * 16);
    }
    int uc = g_ucnt[t] * 16;
    for (int i = tid; i < uc; i += 512) {
        int row = i >> 4, ch = i & 15;
        int node = g_uniq[t * TEE + row];
        CP_ASYNC16(g2 + (uint32_t)(row * 272 + ch * 16),
                   P2 + (size_t)node * 256 + ch * 16);
    }
    if (tid < 32)
        CP_ASYNC16(liBase + buf * 512 + tid * 16,
                   (const char*)(g_li + eb) + tid * 16);
    else if (tid < 64)
        CP_ASYNC16(skBase + buf * 512 + (tid - 32) * 16,
                   (const char*)(g_sortedSnk + eb) + (tid - 32) * 16);
}

__global__ __launch_bounds__(512, 1) void edgeproj_kernel(
    const float* __restrict__ w1, const float* __restrict__ b1,
    const float* __restrict__ w2, const float* __restrict__ b2)
{
    extern __shared__ uint32_t su[];
    const int tid = threadIdx.x;
    const int lid = tid & 31;
    const int wid = tid >> 5;          // 0..15

    // ================= PHASE 1: projection (tid < 256 active) =========
    {
        const uint32_t pBase = smem_u32(su + PA);

        if (tid < 256) {
            int T0 = blockIdx.x;
            if (T0 < NPT_TOT) {
                int b0 = T0 / NPT_B;
                proj_issue(pBase, b0, (T0 - b0 * NPT_B) * 128, tid);
            }
        }
        CP_COMMIT();

        if (tid < 256) {
            for (int i = tid; i < 8 * 32 * 32; i += 256) {
                int s = i >> 10;
                int f = (i >> 5) & 31;
                int l = i & 31;
                int colg = f * 8 + (l >> 2);
                int krow = s * 16 + (l & 3) * 2;
                int koff = (colg >= 128) ? 128 : 0;
                int col = colg & 127;
                uint2 v;
                v.x = pack_h2(w1[(koff + krow) * NH + col],
                              w1[(koff + krow + 1) * NH + col]);
                v.y = pack_h2(w1[(koff + krow + 8) * NH + col],
                              w1[(koff + krow + 9) * NH + col]);
                *(uint2*)(su + PW + 2 * i) = v;
            }
        }

        int it = 0;
        for (int T = blockIdx.x; T < NPT_TOT; T += gridDim.x, it++) {
            const int b = T / NPT_B;
            const int n0 = (T - b * NPT_B) * 128;

            CP_WAIT0();
            __syncthreads();

            if (tid < 256) {
                int Tn = T + gridDim.x;
                if (Tn < NPT_TOT) {
                    int bn = Tn / NPT_B;
                    proj_issue(pBase + ((it + 1) & 1) * 8704 * 4,
                               bn, (Tn - bn * NPT_B) * 128, tid);
                }
            }
            CP_COMMIT();

            if (tid < 256) {
                const uint32_t* A = su + PA + (it & 1) * 8704;
                const int wm = wid >> 1;   // 0..3 (wid<8 here)
                const int wn = wid & 1;
                // split into two row-block halves to keep regs <= 128
                #pragma unroll 1
                for (int mf = 0; mf < 2; mf++) {
                    float acc[16][4];
                    #pragma unroll
                    for (int f = 0; f < 16; f++)
                        #pragma unroll
                        for (int j = 0; j < 4; j++) acc[f][j] = 0.f;

                    const int r0 = wm * 32 + mf * 16 + (lid >> 2);
                    #pragma unroll
                    for (int sg = 0; sg < 8; sg++) {
                        const int kw = sg * 8 + (lid & 3);
                        uint32_t a0 = A[r0 * 68 + kw];
                        uint32_t a1 = A[(r0 + 8) * 68 + kw];
                        uint32_t a2 = A[r0 * 68 + kw + 4];
                        uint32_t a3 = A[(r0 + 8) * 68 + kw + 4];
                        #pragma unroll
                        for (int f = 0; f < 16; f++) {
                            uint2 bp = *(const uint2*)(su + PW +
                                ((sg * 32 + wn * 16 + f) * 32 + lid) * 2);
                            mma_f16(acc[f], a0, a1, a2, a3, bp.x, bp.y);
                        }
                    }
                    #pragma unroll
                    for (int f = 0; f < 16; f++) {
                        const float* c = acc[f];
                        int colg = wn * 128 + f * 8 + (lid & 3) * 2;
                        __half* P = (colg < 128) ? g_P1 : g_P2;
                        int col = colg & 127;
                        int node0 = n0 + r0, node1 = n0 + r0 + 8;
                        if (node0 < NN)
                            *(uint32_t*)(P + ((size_t)b * NN + node0) * NH + col) =
                                pack_h2(c[0], c[1]);
                        if (node1 < NN)
                            *(uint32_t*)(P + ((size_t)b * NN + node1) * NH + col) =
                                pack_h2(c[2], c[3]);
                    }
                }
            }
            __syncthreads();
        }
    }

    // P complete across all blocks before any edge gather
    grid_barrier(tid);

    // ================= PHASE 2: edge =================
    float* sfB2 = (float*)(su + EB2O);
    int* sLiB = (int*)(su + SLIO);
    int* sSnkB = (int*)(su + SSKO);
    float* sfMSG = (float*)(su + EMSO);

    const int wg  = wid >> 1;          // 8 row groups of 16 edges
    const int wc  = wid & 1;           // column half of NM
    const uint32_t gp1Base = smem_u32(su + GP1O);
    const uint32_t gp2Base = smem_u32(su + GP2O);
    const uint32_t liBase  = smem_u32(su + SLIO);
    const uint32_t skBase  = smem_u32(su + SSKO);

    // prologue: tile-0 gather (overlaps weight staging)
    {
        int T0 = blockIdx.x;
        int b0 = T0 / NTE_B;
        edge_issue(gp1Base, gp2Base, liBase, skBase, 0, T0 - b0 * NTE_B, b0, tid);
    }
    CP_COMMIT();

    // stage W2 frags + b2 (overwrites proj regions; safe after barrier)
    for (int i = tid; i < 8 * 8 * 32; i += 512) {
        int s = i >> 8, f = (i >> 5) & 7, l = i & 31;
        int k = s * 16 + (l & 3) * 2, n = f * 8 + (l >> 2);
        uint2 v;
        v.x = pack_h2(w2[k * NM + n],       w2[(k + 1) * NM + n]);
        v.y = pack_h2(w2[(k + 8) * NM + n], w2[(k + 9) * NM + n]);
        *(uint2*)(su + EW2O + 2 * i) = v;
    }
    if (tid < NM) sfB2[tid] = b2[tid];

    // preload b1 as half2 frags: c = 4t + (lid&3) -> halves (2c, 2c+1)
    __half2 b1r[16];
    #pragma unroll
    for (int t = 0; t < 16; t++) {
        int c = 4 * t + (lid & 3);
        b1r[t] = __floats2half2_rn(b1[2 * c], b1[2 * c + 1]);
    }

    const int arq = wg * 16 + (lid >> 2);
    const __half2 hz = __floats2half2_rn(0.f, 0.f);

    int it = 0;
    for (int T = blockIdx.x; T < NTE_TOT; T += gridDim.x, it++) {
        const int b = T / NTE_B;
        const int cb = it & 1;
        float* inc = g_incoming + (size_t)b * NN * NM;

        CP_WAIT0();
        __syncthreads();   // gather bufs cb ready; also guards MSG reuse

        // ---- H = relu(P1 + P2 + b1) directly into A-frag registers
        const uint32_t* G1 = su + GP1O + cb * 8704;
        const uint32_t* G2 = su + GP2O + cb * 8704;
        const int* sLi = sLiB + cb * TEE;
        const int li0 = sLi[arq], li1 = sLi[arq + 8];
        uint32_t hA[8][4];
        #pragma unroll
        for (int sg = 0; sg < 8; sg++) {
            const int c0 = sg * 8 + (lid & 3);
            const int c1 = c0 + 4;
            __half2 v;
            v = __hmax2(__hadd2(__hadd2(*(const __half2*)&G1[arq * 68 + c0],
                                        *(const __half2*)&G2[li0 * 68 + c0]),
                                b1r[2 * sg]), hz);
            hA[sg][0] = *(uint32_t*)&v;
            v = __hmax2(__hadd2(__hadd2(*(const __half2*)&G1[(arq + 8) * 68 + c0],
                                        *(const __half2*)&G2[li1 * 68 + c0]),
                                b1r[2 * sg]), hz);
            hA[sg][1] = *(uint32_t*)&v;
            v = __hmax2(__hadd2(__hadd2(*(const __half2*)&G1[arq * 68 + c1],
                                        *(const __half2*)&G2[li0 * 68 + c1]),
                                b1r[2 * sg + 1]), hz);
            hA[sg][2] = *(uint32_t*)&v;
            v = __hmax2(__hadd2(__hadd2(*(const __half2*)&G1[(arq + 8) * 68 + c1],
                                        *(const __half2*)&G2[li1 * 68 + c1]),
                                b1r[2 * sg + 1]), hz);
            hA[sg][3] = *(uint32_t*)&v;
        }

        // ---- issue next tile's gather (hidden behind GEMM2 + scatter)
        {
            int Tn = T + gridDim.x;
            if (Tn < NTE_TOT) {
                int bn = Tn / NTE_B;
                edge_issue(gp1Base, gp2Base, liBase, skBase,
                           cb ^ 1, Tn - bn * NTE_B, bn, tid);
            }
        }
        CP_COMMIT();

        // ---- GEMM2: [128e x 128h] @ [128h x 64m], A from registers
        float acc2[4][4];
        #pragma unroll
        for (int f = 0; f < 4; f++)
            #pragma unroll
            for (int j = 0; j < 4; j++) acc2[f][j] = 0.f;

        #pragma unroll
        for (int sg = 0; sg < 8; sg++) {
            #pragma unroll
            for (int f = 0; f < 4; f++) {
                uint2 bp = *(const uint2*)(su + EW2O +
                    ((sg * 8 + wc * 4 + f) * 32 + lid) * 2);
                mma_f16(acc2[f], hA[sg][0], hA[sg][1], hA[sg][2], hA[sg][3],
                        bp.x, bp.y);
            }
        }

        // ---- bias -> MSG (fp32)
        #pragma unroll
        for (int f = 0; f < 4; f++) {
            int m = wc * 32 + f * 8 + 2 * (lid & 3);
            float bb0 = sfB2[m], bb1 = sfB2[m + 1];
            sfMSG[arq * 68 + m]           = acc2[f][0] + bb0;
            sfMSG[arq * 68 + m + 1]       = acc2[f][1] + bb1;
            sfMSG[(arq + 8) * 68 + m]     = acc2[f][2] + bb0;
            sfMSG[(arq + 8) * 68 + m + 1] = acc2[f][3] + bb1;
        }
        __syncthreads();   // MSG ready

        // ---- segmented reduction over sorted sinks
        {
            const int* sSnk = sSnkB + cb * TEE;
            const int c = tid & 63;
            const int e0s = (tid >> 6) * 16;
            float part = 0.f;
            int cur = sSnk[e0s];
            #pragma unroll
            for (int j = 0; j < 16; j++) {
                part += sfMSG[(e0s + j) * 68 + c];
                int nxt = (j < 15) ? sSnk[e0s + j + 1] : -1;
                if (nxt != cur) {
                    atomicAdd(inc + (size_t)cur * NM + c, part);
                    part = 0.f;
                    cur = nxt;
                }
            }
        }
        // next iteration's top barrier orders MSG/sSnk reuse
    }
}

// =====================================================================
// Node kernel: full-tile cp.async pipeline (unchanged from R10)
// =====================================================================
#define NW1 0
#define NW2 12288
#define NB1 20480
#define NB2 20608
#define NHS 20736
#define NAB 25088
#define NODE_SMEM_BYTES (46592 * 4)   // 186368

__device__ __forceinline__ void node_issue(uint32_t aBase, int buf, int b,
                                           int n0, int tid) {
    const char* stH = (const char*)(g_statesH + (size_t)b * NN * ND);
    const char* inc = (const char*)(g_incoming + (size_t)b * NN * NM);
    uint32_t abuf = aBase + buf * 10752 * 4;
    uint32_t ibuf = abuf + 6400 * 4;
    #pragma unroll
    for (int i = 0; i < 4; i++) {
        int idx = tid + i * 256;   // 0..1023
        int row = idx >> 4, ch = idx & 15;
        int node = n0 + row;
        if (node < NN) {
            CP_ASYNC16(abuf + (uint32_t)(row * 400 + 128 + ch * 16),
                       stH + (size_t)node * 256 + ch * 16);
            CP_ASYNC16(ibuf + (uint32_t)(row * 272 + ch * 16),
                       inc + (size_t)node * 256 + ch * 16);
        }
    }
}

__global__ __launch_bounds__(256, 1) void node_kernel(
    const float* __restrict__ w1, const float* __restrict__ b1,
    const float* __restrict__ w2, const float* __restrict__ b2)
{
    extern __shared__ uint32_t su[];
    float* sfB1 = (float*)(su + NB1);
    float* sfB2 = (float*)(su + NB2);

    const int tid = threadIdx.x;
    const int lid = tid & 31;
    const int wid = tid >> 5;
    const int wr = wid & 3;
    const int wc = wid >> 2;
    const uint32_t aBase = smem_u32(su + NAB);

    {
        int T0 = blockIdx.x;
        if (T0 < NT_NODE_TOT) {
            int b0 = T0 / NT_NODE_B;
            node_issue(aBase, 0, b0, (T0 - b0 * NT_NODE_B) * 64, tid);
        }
    }
    CP_COMMIT();

    for (int i = tid; i < 12 * 16 * 32; i += 256) {
        int s = i >> 9, f = (i >> 5) & 15, l = i & 31;
        int k = s * 16 + (l & 3) * 2, n = f * 8 + (l >> 2);
        uint2 v;
        v.x = pack_h2(w1[k * NH + n],       w1[(k + 1) * NH + n]);
        v.y = pack_h2(w1[(k + 8) * NH + n], w1[(k + 9) * NH + n]);
        *(uint2*)(su + NW1 + 2 * i) = v;
    }
    for (int i = tid; i < 8 * 16 * 32; i += 256) {
        int s = i >> 9, f = (i >> 5) & 15, l = i & 31;
        int k = s * 16 + (l & 3) * 2, n = f * 8 + (l >> 2);
        uint2 v;
        if (n < NU) {
            v.x = pack_h2(w2[k * NU + n],       w2[(k + 1) * NU + n]);
            v.y = pack_h2(w2[(k + 8) * NU + n], w2[(k + 9) * NU + n]);
        } else v.x = v.y = 0u;
        *(uint2*)(su + NW2 + 2 * i) = v;
    }
    if (tid < NH) sfB1[tid] = b1[tid];
    if (tid < 128) sfB2[tid] = (tid < NU) ? b2[tid] : 0.f;

    const int ar = wr * 16 + (lid >> 2);

    int it = 0;
    for (int T = blockIdx.x; T < NT_NODE_TOT; T += gridDim.x, it++) {
        const int b = T / NT_NODE_B;
        const int n0 = (T - b * NT_NODE_B) * 64;
        const int cb = it & 1;
        float* st = g_states + (size_t)b * NN * ND;
        __half* stH = g_statesH + (size_t)b * NN * ND;
        float* incF = g_incoming + (size_t)b * NN * NM;

        CP_WAIT0();
        __syncthreads();

        {
            uint32_t* A = su + NAB + cb * 10752;
            const uint32_t* INC = A + 6400;
            #pragma unroll
            for (int t = 0; t < 8; t++) {
                int idx = tid + t * 256;
                int row = idx >> 5, c = idx & 31;
                const float* f2 = (const float*)&INC[row * 68 + 2 * c];
                A[row * 100 + c] = pack_h2(f2[0], f2[1]);
            }
            float4 z4 = make_float4(0.f, 0.f, 0.f, 0.f);
            #pragma unroll
            for (int t = 0; t < 4; t++) {
                int idx = tid + t * 256;
                int row = idx >> 4, q = idx & 15;
                int node = n0 + row;
                if (node < NN)
                    *(float4*)(incF + (size_t)node * NM + q * 4) = z4;
            }
        }
        __syncthreads();

        {
            int Tn = T + gridDim.x;
            if (Tn < NT_NODE_TOT) {
                int bn = Tn / NT_NODE_B;
                node_issue(aBase, cb ^ 1, bn, (Tn - bn * NT_NODE_B) * 64, tid);
            }
        }
        CP_COMMIT();

        const uint32_t* A = su + NAB + cb * 10752;
        float acc[8][4];
        #pragma unroll
        for (int f = 0; f < 8; f++)
            #pragma unroll
            for (int j = 0; j < 4; j++) acc[f][j] = 0.f;

        #pragma unroll 4
        for (int sg = 0; sg < 12; sg++) {
            const int kw = sg * 8 + (lid & 3);
            uint32_t a0 = A[ar * 100 + kw];
            uint32_t a1 = A[(ar + 8) * 100 + kw];
            uint32_t a2 = A[ar * 100 + kw + 4];
            uint32_t a3 = A[(ar + 8) * 100 + kw + 4];
            #pragma unroll
            for (int f = 0; f < 8; f++) {
                uint2 bp = *(const uint2*)(su + NW1 +
                    ((sg * 16 + wc * 8 + f) * 32 + lid) * 2);
                mma_f16(acc[f], a0, a1, a2, a3, bp.x, bp.y);
            }
        }

        #pragma unroll
        for (int f = 0; f < 8; f++) {
            int nn0 = wc * 64 + f * 8 + 2 * (lid & 3);
            float bb0 = sfB1[nn0], bb1 = sfB1[nn0 + 1];
            int wcol = wc * 32 + f * 4 + (lid & 3);
            su[NHS + ar * 68 + wcol] =
                pack_h2(fmaxf(acc[f][0] + bb0, 0.f), fmaxf(acc[f][1] + bb1, 0.f));
            su[NHS + (ar + 8) * 68 + wcol] =
                pack_h2(fmaxf(acc[f][2] + bb0, 0.f), fmaxf(acc[f][3] + bb1, 0.f));
        }
        __syncthreads();

        float acc2[8][4];
        #pragma unroll
        for (int f = 0; f < 8; f++)
            #pragma unroll
            for (int j = 0; j < 4; j++) acc2[f][j] = 0.f;

        #pragma unroll 2
        for (int ks = 0; ks < 8; ks++) {
            const int kw = ks * 8 + (lid & 3);
            uint32_t a0 = su[NHS + ar * 68 + kw];
            uint32_t a1 = su[NHS + (ar + 8) * 68 + kw];
            uint32_t a2 = su[NHS + ar * 68 + kw + 4];
            uint32_t a3 = su[NHS + (ar + 8) * 68 + kw + 4];
            #pragma unroll
            for (int f = 0; f < 8; f++) {
                uint2 bp = *(const uint2*)(su + NW2 +
                    ((ks * 16 + wc * 8 + f) * 32 + lid) * 2);
                mma_f16(acc2[f], a0, a1, a2, a3, bp.x, bp.y);
            }
        }

        {
            const int node0 = n0 + ar, node1 = n0 + ar + 8;
            #pragma unroll
            for (int f = 0; f < 8; f++) {
                int cc = wc * 64 + f * 8 + 2 * (lid & 3);
                float bb0 = sfB2[cc], bb1 = sfB2[cc + 1];
                if (cc < NU) {
                    if (node0 < NN) {
                        float* d = st + (size_t)node0 * ND + 2;
                        float nv0 = d[cc] + acc2[f][0] + bb0;
                        float nv1 = d[cc + 1] + acc2[f][1] + bb1;
                        d[cc] = nv0; d[cc + 1] = nv1;
                        *(__half2*)(stH + (size_t)node0 * ND + 2 + cc) =
                            __floats2half2_rn(nv0, nv1);
                    }
                    if (node1 < NN) {
                        float* d = st + (size_t)node1 * ND + 2;
                        float nv0 = d[cc] + acc2[f][2] + bb0;
                        float nv1 = d[cc + 1] + acc2[f][3] + bb1;
                        d[cc] = nv0; d[cc + 1] = nv1;
                        *(__half2*)(stH + (size_t)node1 * ND + 2 + cc) =
                            __floats2half2_rn(nv0, nv1);
                    }
                }
            }
        }
    }
}

// =====================================================================
// Readout: tf32 mma.sync (unchanged)
// =====================================================================
#define EXT_SMEM_FLOATS (32 * 68 + 64 * 132)
#define NSPLIT 8
#define NCHUNK (NN / NSPLIT)   // 1250

__global__ __launch_bounds__(256) void extract_kernel(
    const float* __restrict__ attn, float* __restrict__ out)
{
    extern __shared__ float sm[];
    float* sAt = sm;            // [32][68]
    float* sS  = sm + 32 * 68;  // [64][132]

    const int tid = threadIdx.x;
    const int lid = tid & 31;
    const int wid = tid >> 5;
    const int wq = wid & 1;
    const int wd = wid >> 1;
    const int b = blockIdx.z, qt = blockIdx.y, ns = blockIdx.x;
    const int q0 = qt * 32;
    const int nbeg = ns * NCHUNK;
    const int nend = nbeg + NCHUNK;
    const float* st = g_states + (size_t)b * NN * ND;
    const float* at = attn + ((size_t)b * NQ + q0) * NN;

    float acc[4][4];
    #pragma unroll
    for (int f = 0; f < 4; f++)
        #pragma unroll
        for (int j = 0; j < 4; j++) acc[f][j] = 0.f;

    const int arow = wq * 16 + (lid >> 2);
    const int kq = lid & 3;

    for (int n0 = nbeg; n0 < nend; n0 += 64) {
        __syncthreads();
        #pragma unroll
        for (int t = 0; t < 8; t++) {
            int idx = tid + t * 256;
            int q = idx >> 6, nn = idx & 63;
            int n = n0 + nn;
            sAt[q * 68 + nn] = (n < nend) ? tf32f(at[q * NN + n]) : 0.f;
        }
        #pragma unroll
        for (int t = 0; t < 32; t++) {
            int idx = tid + t * 256;
            int nn = idx >> 7, d = idx & 127;
            int n = n0 + nn;
            sS[nn * 132 + d] = (n < nend) ? tf32f(st[(size_t)n * ND + d]) : 0.f;
        }
        __syncthreads();

        #pragma unroll
        for (int ks = 0; ks < 8; ks++) {
            const int k0 = ks * 8;
            uint32_t a0 = __float_as_uint(sAt[arow * 68 + k0 + kq]);
            uint32_t a1 = __float_as_uint(sAt[(arow + 8) * 68 + k0 + kq]);
            uint32_t a2 = __float_as_uint(sAt[arow * 68 + k0 + 4 + kq]);
            uint32_t a3 = __float_as_uint(sAt[(arow + 8) * 68 + k0 + 4 + kq]);
            #pragma unroll
            for (int f = 0; f < 4; f++) {
                int n = wd * 32 + f * 8 + (lid >> 2);
                uint32_t b0 = __float_as_uint(sS[(k0 + kq) * 132 + n]);
                uint32_t b1 = __float_as_uint(sS[(k0 + 4 + kq) * 132 + n]);
                mma_tf32(acc[f], a0, a1, a2, a3, b0, b1);
            }
        }
    }

    #pragma unroll
    for (int f = 0; f < 4; f++) {
        int d = wd * 32 + f * 8 + (lid & 3) * 2;
        int q = q0 + wq * 16 + (lid >> 2);
        float* drow = out + ((size_t)(b * NQ + q)) * OUTC + NP + d;
        atomicAdd(drow,     acc[f][0]);
        atomicAdd(drow + 1, acc[f][1]);
        float* drow2 = out + ((size_t)(b * NQ + q + 8)) * OUTC + NP + d;
        atomicAdd(drow2,     acc[f][2]);
        atomicAdd(drow2 + 1, acc[f][3]);
    }
}

// =====================================================================
extern "C" void kernel_launch(void* const* d_in, const int* in_sizes, int n_in,
                              void* d_out, int out_size)
{
    const float* nodes = (const float*)d_in[0];
    const float* poses = (const float*)d_in[1];
    const float* attn  = (const float*)d_in[2];
    const int*   esrc  = (const int*)d_in[3];
    const int*   esnk  = (const int*)d_in[4];
    const float* w1e   = (const float*)d_in[5];
    const float* b1e   = (const float*)d_in[6];
    const float* w2e   = (const float*)d_in[7];
    const float* b2e   = (const float*)d_in[8];
    const float* w1n   = (const float*)d_in[9];
    const float* b1n   = (const float*)d_in[10];
    const float* w2n   = (const float*)d_in[11];
    const float* b2n   = (const float*)d_in[12];
    float* out = (float*)d_out;

    cudaFuncSetAttribute(edgeproj_kernel, cudaFuncAttributeMaxDynamicSharedMemorySize,
                         EDGE_SMEM_BYTES);
    cudaFuncSetAttribute(node_kernel, cudaFuncAttributeMaxDynamicSharedMemorySize,
                         NODE_SMEM_BYTES);

    // copy + fp16 mirror + csr count zero (fused)
    copy_states_kernel<<<(NB * NN * ND / 4 + 255) / 256, 256>>>(nodes);

    // CSR chain (hist also zeroes g_incoming)
    csr_hist_kernel<<<(NE + 255) / 256, 256>>>(esnk);
    csr_scan_kernel<<<1, 1024>>>();
    csr_scatter_kernel<<<(NE + 255) / 256, 256>>>(esrc, esnk);
    tile_meta_kernel<<<NTE_B, TEE>>>();

    for (int s = 0; s < 3; s++) {
        edgeproj_kernel<<<GRID_PERS, 512, EDGE_SMEM_BYTES>>>(w1e, b1e, w2e, b2e);
        node_kernel<<<GRID_PERS, 256, NODE_SMEM_BYTES>>>(w1n, b1n, w2n, b2n);
    }
    init_out_kernel<<<(NB * NQ * OUTC + 255) / 256, 256>>>(poses, out);
    extract_kernel<<<dim3(NSPLIT, NQ / 32, NB), 256, EXT_SMEM_FLOATS * 4>>>(attn, out);
}

// round 12
// speedup vs baseline: 1.0147x; 1.0147x over previous
#include <cuda_runtime.h>
#include <cuda_fp16.h>
#include <cstdint>

#define NB 4
#define NN 10000
#define NE 160000
#define NQ 256
#define ND 128
#define NM 64
#define NU 126
#define NH 128
#define NP 7
#define OUTC (NP + ND)   // 135

#define TEE 128                    // edges per edge-tile
#define NTE_B (NE / TEE)           // 1250
#define NTE_TOT (NTE_B * NB)       // 5000

#define NT_NODE_B 157              // ceil(10000/64)
#define NT_NODE_TOT (NT_NODE_B * NB)

#define NPT_B 79                   // ceil(10000/128) proj tiles per batch
#define NPT_TOT (NPT_B * NB)       // 316

// -------- scratch (static device globals: allocation-free) --------
__device__ float g_states[NB * NN * ND];                  // 20.5 MB
__device__ __align__(16) __half g_statesH[NB * NN * ND];  // 10.2 MB fp16 mirror
__device__ float g_incoming[NB * NN * NM];                // 10.2 MB
__device__ __align__(16) __half g_P1[NB * NN * NH];       // src projections
__device__ __align__(16) __half g_P2[NB * NN * NH];       // snk projections
// CSR + tile metadata
__device__ int g_count[NN];
__device__ int g_cur[NN];
__device__ int g_sortedSrc[NE];
__device__ int g_sortedSnk[NE];
__device__ int g_li[NE];               // per-edge local unique-sink index
__device__ int g_uniq[NTE_B * TEE];    // per-tile unique sink list
__device__ int g_ucnt[NTE_B];          // per-tile unique count

// ============================ helpers ============================
__device__ __forceinline__ uint32_t smem_u32(const void* p) {
    uint32_t a;
    asm("{ .reg .u64 t; cvta.to.shared.u64 t, %1; cvt.u32.u64 %0, t; }"
        : "=r"(a) : "l"(p));
    return a;
}
__device__ __forceinline__ uint32_t pack_h2(float a, float b) {
    __half2 h = __floats2half2_rn(a, b);
    return *reinterpret_cast<uint32_t*>(&h);
}
__device__ __forceinline__ float tf32f(float f) {
    uint32_t r;
    asm("cvt.rna.tf32.f32 %0, %1;" : "=r"(r) : "f"(f));
    return __uint_as_float(r);
}
__device__ __forceinline__ void mma_f16(float* c, uint32_t a0, uint32_t a1,
                                        uint32_t a2, uint32_t a3,
                                        uint32_t b0, uint32_t b1) {
    asm volatile(
        "mma.sync.aligned.m16n8k16.row.col.f32.f16.f16.f32 "
        "{%0,%1,%2,%3}, {%4,%5,%6,%7}, {%8,%9}, {%0,%1,%2,%3};"
        : "+f"(c[0]), "+f"(c[1]), "+f"(c[2]), "+f"(c[3])
        : "r"(a0), "r"(a1), "r"(a2), "r"(a3), "r"(b0), "r"(b1));
}
__device__ __forceinline__ void mma_tf32(float* c, uint32_t a0, uint32_t a1,
                                         uint32_t a2, uint32_t a3,
                                         uint32_t b0, uint32_t b1) {
    asm volatile(
        "mma.sync.aligned.m16n8k8.row.col.f32.tf32.tf32.f32 "
        "{%0,%1,%2,%3}, {%4,%5,%6,%7}, {%8,%9}, {%0,%1,%2,%3};"
        : "+f"(c[0]), "+f"(c[1]), "+f"(c[2]), "+f"(c[3])
        : "r"(a0), "r"(a1), "r"(a2), "r"(a3), "r"(b0), "r"(b1));
}
#define CP_ASYNC16(dst, src) \
    asm volatile("cp.async.cg.shared.global [%0], [%1], 16;" \
                 :: "r"(dst), "l"(src) : "memory")
#define CP_COMMIT() asm volatile("cp.async.commit_group;" ::: "memory")
#define CP_WAIT0()  asm volatile("cp.async.wait_group 0;" ::: "memory")

// -------- utility kernels --------
// copy + fp16 mirror + csr count zero + out-pose init (all independent ranges)
__global__ void copy_states_kernel(const float* __restrict__ src,
                                   const float* __restrict__ poses,
                                   float* __restrict__ out) {
    int i = blockIdx.x * blockDim.x + threadIdx.x;
    const int n = NB * NN * ND / 4;
    if (i < n) {
        float4 v = reinterpret_cast<const float4*>(src)[i];
        reinterpret_cast<float4*>(g_states)[i] = v;
        __half2* mh = reinterpret_cast<__half2*>(g_statesH);
        mh[2 * i]     = __floats2half2_rn(v.x, v.y);
        mh[2 * i + 1] = __floats2half2_rn(v.z, v.w);
    }
    if (i < NN) g_count[i] = 0;
    if (i < NB * NQ * OUTC) {
        int r = i / OUTC, c = i - r * OUTC;
        out[i] = (c < NP) ? poses[r * NP + c] : 0.f;
    }
}

// -------- CSR build (once per launch; graph static) --------
// hist + fused zero_incoming: grid is exactly 625*256 = 160000 threads
__global__ void csr_hist_kernel(const int* __restrict__ esnk) {
    int i = blockIdx.x * blockDim.x + threadIdx.x;
    float4 z = make_float4(0.f, 0.f, 0.f, 0.f);
    #pragma unroll
    for (int t = 0; t < 4; t++) {
        int j = i + t * 160000;
        if (j < NB * NN * NM / 4)
            reinterpret_cast<float4*>(g_incoming)[j] = z;
    }
    if (i < NE) atomicAdd(&g_count[esnk[i]], 1);
}
__global__ void csr_scan_kernel() {
    __shared__ int part[1024];
    int t = threadIdx.x;
    int beg = t * 10;
    int end = beg + 10 < NN ? beg + 10 : NN;
    int s = 0;
    for (int i = beg; i < end; i++) s += g_count[i];
    part[t] = s;
    __syncthreads();
    for (int d = 1; d < 1024; d <<= 1) {
        int v = (t >= d) ? part[t - d] : 0;
        __syncthreads();
        part[t] += v;
        __syncthreads();
    }
    int base = (t > 0) ? part[t - 1] : 0;
    for (int i = beg; i < end; i++) {
        g_cur[i] = base;
        base += g_count[i];
    }
}
__global__ void csr_scatter_kernel(const int* __restrict__ esrc,
                                   const int* __restrict__ esnk) {
    int i = blockIdx.x * blockDim.x + threadIdx.x;
    if (i < NE) {
        int s = esnk[i];
        int p = atomicAdd(&g_cur[s], 1);
        g_sortedSrc[p] = esrc[i];
        g_sortedSnk[p] = s;
    }
}
__global__ void tile_meta_kernel() {
    __shared__ int fl[TEE];
    int t = blockIdx.x, tid = threadIdx.x;
    int e = t * TEE + tid;
    int s = g_sortedSnk[e];
    int flag = (tid == 0) || (s != g_sortedSnk[e - 1]);
    fl[tid] = flag;
    __syncthreads();
    for (int d = 1; d < TEE; d <<= 1) {
        int v = (tid >= d) ? fl[tid - d] : 0;
        __syncthreads();
        fl[tid] += v;
        __syncthreads();
    }
    int li = fl[tid] - 1;
    g_li[e] = li;
    if (flag) g_uniq[t * TEE + li] = s;
    if (tid == TEE - 1) g_ucnt[t] = fl[tid];
}

// =====================================================================
// Projection kernel (512 thr, 16 warps = 4 row-groups x 4 col-quarters):
// P1 = statesH @ W1top, P2 = statesH @ W1bot (fp16 out)
// smem: PW [0,16384) frags [8 sg][32 nf][32][2]; PA [16384,+2*8704)
// =====================================================================
#define PW 0
#define PA 16384
#define PROJ_SMEM_BYTES ((16384 + 2 * 8704) * 4)   // 135168

__device__ __forceinline__ void proj_issue(uint32_t aBase, int b, int n0, int tid) {
    const __half* stH = g_statesH + (size_t)b * NN * ND;
    #pragma unroll
    for (int t = 0; t < 4; t++) {
        int idx = tid + t * 512;       // 0..2047
        int row = idx >> 4, ch = idx & 15;
        int node = n0 + row;
        if (node >= NN) node = NN - 1;   // clamp; stores are guarded
        uint32_t dst = aBase + row * 272 + ch * 16;
        CP_ASYNC16(dst, stH + (size_t)node * ND + ch * 8);
    }
}

__global__ __launch_bounds__(512, 1) void proj_kernel(
    const float* __restrict__ w1)
{
    extern __shared__ uint32_t su[];
    const int tid = threadIdx.x;
    const int lid = tid & 31;
    const int wid = tid >> 5;     // 0..15
    const int wm = wid >> 2;      // 4 row groups of 32 nodes
    const int wq = wid & 3;       // 4 col quarters (64 cols = 8 nf each)
    const uint32_t aBase0 = smem_u32(su + PA);

    {
        int T0 = blockIdx.x;
        if (T0 < NPT_TOT) {
            int b0 = T0 / NPT_B;
            proj_issue(aBase0, b0, (T0 - b0 * NPT_B) * 128, tid);
        }
    }
    CP_COMMIT();

    for (int i = tid; i < 8 * 32 * 32; i += 512) {
        int s = i >> 10;
        int f = (i >> 5) & 31;
        int l = i & 31;
        int colg = f * 8 + (l >> 2);
        int krow = s * 16 + (l & 3) * 2;
        int koff = (colg >= 128) ? 128 : 0;
        int col = colg & 127;
        uint2 v;
        v.x = pack_h2(w1[(koff + krow) * NH + col],     w1[(koff + krow + 1) * NH + col]);
        v.y = pack_h2(w1[(koff + krow + 8) * NH + col], w1[(koff + krow + 9) * NH + col]);
        *(uint2*)(su + PW + 2 * i) = v;
    }

    int it = 0;
    for (int T = blockIdx.x; T < NPT_TOT; T += gridDim.x, it++) {
        const int b = T / NPT_B;
        const int n0 = (T - b * NPT_B) * 128;

        CP_WAIT0();
        __syncthreads();

        {
            int Tn = T + gridDim.x;
            if (Tn < NPT_TOT) {
                int bn = Tn / NPT_B;
                proj_issue(aBase0 + ((it + 1) & 1) * 8704 * 4,
                           bn, (Tn - bn * NPT_B) * 128, tid);
            }
        }
        CP_COMMIT();

        const uint32_t* A = su + PA + (it & 1) * 8704;
        #pragma unroll
        for (int mf = 0; mf < 2; mf++) {
            float acc[8][4];
            #pragma unroll
            for (int f = 0; f < 8; f++)
                #pragma unroll
                for (int j = 0; j < 4; j++) acc[f][j] = 0.f;

            const int r0 = wm * 32 + mf * 16 + (lid >> 2);
            #pragma unroll
            for (int sg = 0; sg < 8; sg++) {
                const int kw = sg * 8 + (lid & 3);
                uint32_t a0 = A[r0 * 68 + kw];
                uint32_t a1 = A[(r0 + 8) * 68 + kw];
                uint32_t a2 = A[r0 * 68 + kw + 4];
                uint32_t a3 = A[(r0 + 8) * 68 + kw + 4];
                #pragma unroll
                for (int f = 0; f < 8; f++) {
                    uint2 bp = *(const uint2*)(su + PW +
                        ((sg * 32 + wq * 8 + f) * 32 + lid) * 2);
                    mma_f16(acc[f], a0, a1, a2, a3, bp.x, bp.y);
                }
            }
            #pragma unroll
            for (int f = 0; f < 8; f++) {
                const float* c = acc[f];
                int colg = wq * 64 + f * 8 + (lid & 3) * 2;
                __half* P = (colg < 128) ? g_P1 : g_P2;
                int col = colg & 127;
                int node0 = n0 + r0, node1 = n0 + r0 + 8;
                if (node0 < NN)
                    *(uint32_t*)(P + ((size_t)b * NN + node0) * NH + col) =
                        pack_h2(c[0], c[1]);
                if (node1 < NN)
                    *(uint32_t*)(P + ((size_t)b * NN + node1) * NH + col) =
                        pack_h2(c[2], c[3]);
            }
        }
        __syncthreads();
    }
}

// =====================================================================
// Edge kernel (unchanged from R10 champion): gather P1[src] + P2[unique],
// H in registers, GEMM2, segmented scatter. 512 thr, 1 CTA/SM.
// =====================================================================
#define EW2O  0
#define EB2O  4096
#define SLIO  4160
#define SSKO  4416
#define EMSO  4672
#define GP1O  13376
#define GP2O  30784
#define EDGE_SMEM_BYTES (48192 * 4)   // 192768

__device__ __forceinline__ void edge_issue(
    uint32_t gp1Base, uint32_t gp2Base, uint32_t liBase, uint32_t skBase,
    int buf, int t, int b, int tid)
{
    const int eb = t * TEE;
    const char* P1 = (const char*)(g_P1 + (size_t)b * NN * NH);
    const char* P2 = (const char*)(g_P2 + (size_t)b * NN * NH);
    uint32_t g1 = gp1Base + buf * 8704 * 4;
    uint32_t g2 = gp2Base + buf * 8704 * 4;
    #pragma unroll
    for (int i = 0; i < 4; i++) {
        int idx = tid + i * 512;        // 0..2047
        int row = idx >> 4, ch = idx & 15;
        int node = g_sortedSrc[eb + row];
        CP_ASYNC16(g1 + (uint32_t)(row * 272 + ch * 16),
                   P1 + (size_t)node * 256 + ch * 16);
    }
    int uc = g_ucnt[t] * 16;
    for (int i = tid; i < uc; i += 512) {
        int row = i >> 4, ch = i & 15;
        int node = g_uniq[t * TEE + row];
        CP_ASYNC16(g2 + (uint32_t)(row * 272 + ch * 16),
                   P2 + (size_t)node * 256 + ch * 16);
    }
    if (tid < 32)
        CP_ASYNC16(liBase + buf * 512 + tid * 16,
                   (const char*)(g_li + eb) + tid * 16);
    else if (tid < 64)
        CP_ASYNC16(skBase + buf * 512 + (tid - 32) * 16,
                   (const char*)(g_sortedSnk + eb) + (tid - 32) * 16);
}

__global__ __launch_bounds__(512, 1) void edge_kernel(
    const float* __restrict__ b1,
    const float* __restrict__ w2, const float* __restrict__ b2)
{
    extern __shared__ uint32_t su[];
    float* sfB2 = (float*)(su + EB2O);
    int* sLiB = (int*)(su + SLIO);
    int* sSnkB = (int*)(su + SSKO);
    float* sfMSG = (float*)(su + EMSO);

    const int tid = threadIdx.x;
    const int lid = tid & 31;
    const int wid = tid >> 5;          // 0..15
    const int wg  = wid >> 1;          // 8 row groups of 16 edges
    const int wc  = wid & 1;           // column half of NM
    const uint32_t gp1Base = smem_u32(su + GP1O);
    const uint32_t gp2Base = smem_u32(su + GP2O);
    const uint32_t liBase  = smem_u32(su + SLIO);
    const uint32_t skBase  = smem_u32(su + SSKO);

    {
        int T0 = blockIdx.x;
        int b0 = T0 / NTE_B;
        edge_issue(gp1Base, gp2Base, liBase, skBase, 0, T0 - b0 * NTE_B, b0, tid);
    }
    CP_COMMIT();

    for (int i = tid; i < 8 * 8 * 32; i += 512) {
        int s = i >> 8, f = (i >> 5) & 7, l = i & 31;
        int k = s * 16 + (l & 3) * 2, n = f * 8 + (l >> 2);
        uint2 v;
        v.x = pack_h2(w2[k * NM + n],       w2[(k + 1) * NM + n]);
        v.y = pack_h2(w2[(k + 8) * NM + n], w2[(k + 9) * NM + n]);
        *(uint2*)(su + EW2O + 2 * i) = v;
    }
    if (tid < NM) sfB2[tid] = b2[tid];

    __half2 b1r[16];
    #pragma unroll
    for (int t = 0; t < 16; t++) {
        int c = 4 * t + (lid & 3);
        b1r[t] = __floats2half2_rn(b1[2 * c], b1[2 * c + 1]);
    }

    const int arq = wg * 16 + (lid >> 2);
    const __half2 hz = __floats2half2_rn(0.f, 0.f);

    int it = 0;
    for (int T = blockIdx.x; T < NTE_TOT; T += gridDim.x, it++) {
        const int b = T / NTE_B;
        const int cb = it & 1;
        float* inc = g_incoming + (size_t)b * NN * NM;

        CP_WAIT0();
        __syncthreads();

        const uint32_t* G1 = su + GP1O + cb * 8704;
        const uint32_t* G2 = su + GP2O + cb * 8704;
        const int* sLi = sLiB + cb * TEE;
        const int li0 = sLi[arq], li1 = sLi[arq + 8];
        uint32_t hA[8][4];
        #pragma unroll
        for (int sg = 0; sg < 8; sg++) {
            const int c0 = sg * 8 + (lid & 3);
            const int c1 = c0 + 4;
            __half2 v;
            v = __hmax2(__hadd2(__hadd2(*(const __half2*)&G1[arq * 68 + c0],
                                        *(const __half2*)&G2[li0 * 68 + c0]),
                                b1r[2 * sg]), hz);
            hA[sg][0] = *(uint32_t*)&v;
            v = __hmax2(__hadd2(__hadd2(*(const __half2*)&G1[(arq + 8) * 68 + c0],
                                        *(const __half2*)&G2[li1 * 68 + c0]),
                                b1r[2 * sg]), hz);
            hA[sg][1] = *(uint32_t*)&v;
            v = __hmax2(__hadd2(__hadd2(*(const __half2*)&G1[arq * 68 + c1],
                                        *(const __half2*)&G2[li0 * 68 + c1]),
                                b1r[2 * sg + 1]), hz);
            hA[sg][2] = *(uint32_t*)&v;
            v = __hmax2(__hadd2(__hadd2(*(const __half2*)&G1[(arq + 8) * 68 + c1],
                                        *(const __half2*)&G2[li1 * 68 + c1]),
                                b1r[2 * sg + 1]), hz);
            hA[sg][3] = *(uint32_t*)&v;
        }

        {
            int Tn = T + gridDim.x;
            if (Tn < NTE_TOT) {
                int bn = Tn / NTE_B;
                edge_issue(gp1Base, gp2Base, liBase, skBase,
                           cb ^ 1, Tn - bn * NTE_B, bn, tid);
            }
        }
        CP_COMMIT();

        float acc2[4][4];
        #pragma unroll
        for (int f = 0; f < 4; f++)
            #pragma unroll
            for (int j = 0; j < 4; j++) acc2[f][j] = 0.f;

        #pragma unroll
        for (int sg = 0; sg < 8; sg++) {
            #pragma unroll
            for (int f = 0; f < 4; f++) {
                uint2 bp = *(const uint2*)(su + EW2O +
                    ((sg * 8 + wc * 4 + f) * 32 + lid) * 2);
                mma_f16(acc2[f], hA[sg][0], hA[sg][1], hA[sg][2], hA[sg][3],
                        bp.x, bp.y);
            }
        }

        #pragma unroll
        for (int f = 0; f < 4; f++) {
            int m = wc * 32 + f * 8 + 2 * (lid & 3);
            float bb0 = sfB2[m], bb1 = sfB2[m + 1];
            sfMSG[arq * 68 + m]           = acc2[f][0] + bb0;
            sfMSG[arq * 68 + m + 1]       = acc2[f][1] + bb1;
            sfMSG[(arq + 8) * 68 + m]     = acc2[f][2] + bb0;
            sfMSG[(arq + 8) * 68 + m + 1] = acc2[f][3] + bb1;
        }
        __syncthreads();

        {
            const int* sSnk = sSnkB + cb * TEE;
            const int c = tid & 63;
            const int e0s = (tid >> 6) * 16;
            float part = 0.f;
            int cur = sSnk[e0s];
            #pragma unroll
            for (int j = 0; j < 16; j++) {
                part += sfMSG[(e0s + j) * 68 + c];
                int nxt = (j < 15) ? sSnk[e0s + j + 1] : -1;
                if (nxt != cur) {
                    atomicAdd(inc + (size_t)cur * NM + c, part);
                    part = 0.f;
                    cur = nxt;
                }
            }
        }
    }
}

// =====================================================================
// Node kernel: 512 thr (16 warps = 4 row x 4 col groups), full-tile
// cp.async pipeline, zeroes incoming, maintains fp16 mirror.
// smem identical layout to R10 node.
// =====================================================================
#define NW1 0
#define NW2 12288
#define NB1 20480
#define NB2 20608
#define NHS 20736
#define NAB 25088
#define NODE_SMEM_BYTES (46592 * 4)   // 186368

__device__ __forceinline__ void node_issue(uint32_t aBase, int buf, int b,
                                           int n0, int tid) {
    const char* stH = (const char*)(g_statesH + (size_t)b * NN * ND);
    const char* inc = (const char*)(g_incoming + (size_t)b * NN * NM);
    uint32_t abuf = aBase + buf * 10752 * 4;
    uint32_t ibuf = abuf + 6400 * 4;
    #pragma unroll
    for (int i = 0; i < 2; i++) {
        int idx = tid + i * 512;   // 0..1023
        int row = idx >> 4, ch = idx & 15;
        int node = n0 + row;
        if (node < NN) {
            CP_ASYNC16(abuf + (uint32_t)(row * 400 + 128 + ch * 16),
                       stH + (size_t)node * 256 + ch * 16);
            CP_ASYNC16(ibuf + (uint32_t)(row * 272 + ch * 16),
                       inc + (size_t)node * 256 + ch * 16);
        }
    }
}

__global__ __launch_bounds__(512, 1) void node_kernel(
    const float* __restrict__ w1, const float* __restrict__ b1,
    const float* __restrict__ w2, const float* __restrict__ b2)
{
    extern __shared__ uint32_t su[];
    float* sfB1 = (float*)(su + NB1);
    float* sfB2 = (float*)(su + NB2);

    const int tid = threadIdx.x;
    const int lid = tid & 31;
    const int wid = tid >> 5;     // 0..15
    const int wr = wid & 3;       // 4 row groups (16 nodes each)
    const int wc = wid >> 2;      // 4 col groups (32 cols each)
    const uint32_t aBase = smem_u32(su + NAB);

    {
        int T0 = blockIdx.x;
        if (T0 < NT_NODE_TOT) {
            int b0 = T0 / NT_NODE_B;
            node_issue(aBase, 0, b0, (T0 - b0 * NT_NODE_B) * 64, tid);
        }
    }
    CP_COMMIT();

    for (int i = tid; i < 12 * 16 * 32; i += 512) {
        int s = i >> 9, f = (i >> 5) & 15, l = i & 31;
        int k = s * 16 + (l & 3) * 2, n = f * 8 + (l >> 2);
        uint2 v;
        v.x = pack_h2(w1[k * NH + n],       w1[(k + 1) * NH + n]);
        v.y = pack_h2(w1[(k + 8) * NH + n], w1[(k + 9) * NH + n]);
        *(uint2*)(su + NW1 + 2 * i) = v;
    }
    for (int i = tid; i < 8 * 16 * 32; i += 512) {
        int s = i >> 9, f = (i >> 5) & 15, l = i & 31;
        int k = s * 16 + (l & 3) * 2, n = f * 8 + (l >> 2);
        uint2 v;
        if (n < NU) {
            v.x = pack_h2(w2[k * NU + n],       w2[(k + 1) * NU + n]);
            v.y = pack_h2(w2[(k + 8) * NU + n], w2[(k + 9) * NU + n]);
        } else v.x = v.y = 0u;
        *(uint2*)(su + NW2 + 2 * i) = v;
    }
    if (tid < NH) sfB1[tid] = b1[tid];
    if (tid < 128) sfB2[tid] = (tid < NU) ? b2[tid] : 0.f;

    const int ar = wr * 16 + (lid >> 2);

    int it = 0;
    for (int T = blockIdx.x; T < NT_NODE_TOT; T += gridDim.x, it++) {
        const int b = T / NT_NODE_B;
        const int n0 = (T - b * NT_NODE_B) * 64;
        const int cb = it & 1;
        float* st = g_states + (size_t)b * NN * ND;
        __half* stH = g_statesH + (size_t)b * NN * ND;
        float* incF = g_incoming + (size_t)b * NN * NM;

        CP_WAIT0();
        __syncthreads();

        // convert incoming fp32 -> A cols 0..31 (u32); zero global rows
        {
            uint32_t* A = su + NAB + cb * 10752;
            const uint32_t* INC = A + 6400;
            #pragma unroll
            for (int t = 0; t < 4; t++) {
                int idx = tid + t * 512;   // 0..2047
                int row = idx >> 5, c = idx & 31;
                const float* f2 = (const float*)&INC[row * 68 + 2 * c];
                A[row * 100 + c] = pack_h2(f2[0], f2[1]);
            }
            float4 z4 = make_float4(0.f, 0.f, 0.f, 0.f);
            #pragma unroll
            for (int t = 0; t < 2; t++) {
                int idx = tid + t * 512;   // 0..1023
                int row = idx >> 4, q = idx & 15;
                int node = n0 + row;
                if (node < NN)
                    *(float4*)(incF + (size_t)node * NM + q * 4) = z4;
            }
        }
        __syncthreads();

        {
            int Tn = T + gridDim.x;
            if (Tn < NT_NODE_TOT) {
                int bn = Tn / NT_NODE_B;
                node_issue(aBase, cb ^ 1, bn, (Tn - bn * NT_NODE_B) * 64, tid);
            }
        }
        CP_COMMIT();

        // GEMM1: [64 x 192] @ [192 x 128], 12 K-steps; 4 nf per warp
        const uint32_t* A = su + NAB + cb * 10752;
        float acc[4][4];
        #pragma unroll
        for (int f = 0; f < 4; f++)
            #pragma unroll
            for (int j = 0; j < 4; j++) acc[f][j] = 0.f;

        #pragma unroll 4
        for (int sg = 0; sg < 12; sg++) {
            const int kw = sg * 8 + (lid & 3);
            uint32_t a0 = A[ar * 100 + kw];
            uint32_t a1 = A[(ar + 8) * 100 + kw];
            uint32_t a2 = A[ar * 100 + kw + 4];
            uint32_t a3 = A[(ar + 8) * 100 + kw + 4];
            #pragma unroll
            for (int f = 0; f < 4; f++) {
                uint2 bp = *(const uint2*)(su + NW1 +
                    ((sg * 16 + wc * 4 + f) * 32 + lid) * 2);
                mma_f16(acc[f], a0, a1, a2, a3, bp.x, bp.y);
            }
        }

        // epilogue1: bias + relu -> H (fp16); warp covers 32 cols
        #pragma unroll
        for (int f = 0; f < 4; f++) {
            int nn0 = wc * 32 + f * 8 + 2 * (lid & 3);
            float bb0 = sfB1[nn0], bb1 = sfB1[nn0 + 1];
            int wcol = wc * 16 + f * 4 + (lid & 3);
            su[NHS + ar * 68 + wcol] =
                pack_h2(fmaxf(acc[f][0] + bb0, 0.f), fmaxf(acc[f][1] + bb1, 0.f));
            su[NHS + (ar + 8) * 68 + wcol] =
                pack_h2(fmaxf(acc[f][2] + bb0, 0.f), fmaxf(acc[f][3] + bb1, 0.f));
        }
        __syncthreads();

        // GEMM2: [64 x 128] @ [128 x 128(padded 126)]; 4 nf per warp
        float acc2[4][4];
        #pragma unroll
        for (int f = 0; f < 4; f++)
            #pragma unroll
            for (int j = 0; j < 4; j++) acc2[f][j] = 0.f;

        #pragma unroll 4
        for (int ks = 0; ks < 8; ks++) {
            const int kw = ks * 8 + (lid & 3);
            uint32_t a0 = su[NHS + ar * 68 + kw];
            uint32_t a1 = su[NHS + (ar + 8) * 68 + kw];
            uint32_t a2 = su[NHS + ar * 68 + kw + 4];
            uint32_t a3 = su[NHS + (ar + 8) * 68 + kw + 4];
            #pragma unroll
            for (int f = 0; f < 4; f++) {
                uint2 bp = *(const uint2*)(su + NW2 +
                    ((ks * 16 + wc * 4 + f) * 32 + lid) * 2);
                mma_f16(acc2[f], a0, a1, a2, a3, bp.x, bp.y);
            }
        }

        // in-place state update + fp16 mirror (exclusive ownership)
        {
            const int node0 = n0 + ar, node1 = n0 + ar + 8;
            #pragma unroll
            for (int f = 0; f < 4; f++) {
                int cc = wc * 32 + f * 8 + 2 * (lid & 3);
                float bb0 = sfB2[cc], bb1 = sfB2[cc + 1];
                if (cc < NU) {
                    if (node0 < NN) {
                        float* d = st + (size_t)node0 * ND + 2;
                        float nv0 = d[cc] + acc2[f][0] + bb0;
                        float nv1 = d[cc + 1] + acc2[f][1] + bb1;
                        d[cc] = nv0; d[cc + 1] = nv1;
                        *(__half2*)(stH + (size_t)node0 * ND + 2 + cc) =
                            __floats2half2_rn(nv0, nv1);
                    }
                    if (node1 < NN) {
                        float* d = st + (size_t)node1 * ND + 2;
                        float nv0 = d[cc] + acc2[f][2] + bb0;
                        float nv1 = d[cc + 1] + acc2[f][3] + bb1;
                        d[cc] = nv0; d[cc + 1] = nv1;
                        *(__half2*)(stH + (size_t)node1 * ND + 2 + cc) =
                            __floats2half2_rn(nv0, nv1);
                    }
                }
            }
        }
        // next top barrier guards NHS reuse
    }
}

// =====================================================================
// Readout: tf32 mma.sync (unchanged)
// =====================================================================
#define EXT_SMEM_FLOATS (32 * 68 + 64 * 132)
#define NSPLIT 8
#define NCHUNK (NN / NSPLIT)   // 1250

__global__ __launch_bounds__(256) void extract_kernel(
    const float* __restrict__ attn, float* __restrict__ out)
{
    extern __shared__ float sm[];
    float* sAt = sm;            // [32][68]
    float* sS  = sm + 32 * 68;  // [64][132]

    const int tid = threadIdx.x;
    const int lid = tid & 31;
    const int wid = tid >> 5;
    const int wq = wid & 1;
    const int wd = wid >> 1;
    const int b = blockIdx.z, qt = blockIdx.y, ns = blockIdx.x;
    const int q0 = qt * 32;
    const int nbeg = ns * NCHUNK;
    const int nend = nbeg + NCHUNK;
    const float* st = g_states + (size_t)b * NN * ND;
    const float* at = attn + ((size_t)b * NQ + q0) * NN;

    float acc[4][4];
    #pragma unroll
    for (int f = 0; f < 4; f++)
        #pragma unroll
        for (int j = 0; j < 4; j++) acc[f][j] = 0.f;

    const int arow = wq * 16 + (lid >> 2);
    const int kq = lid & 3;

    for (int n0 = nbeg; n0 < nend; n0 += 64) {
        __syncthreads();
        #pragma unroll
        for (int t = 0; t < 8; t++) {
            int idx = tid + t * 256;
            int q = idx >> 6, nn = idx & 63;
            int n = n0 + nn;
            sAt[q * 68 + nn] = (n < nend) ? tf32f(at[q * NN + n]) : 0.f;
        }
        #pragma unroll
        for (int t = 0; t < 32; t++) {
            int idx = tid + t * 256;
            int nn = idx >> 7, d = idx & 127;
            int n = n0 + nn;
            sS[nn * 132 + d] = (n < nend) ? tf32f(st[(size_t)n * ND + d]) : 0.f;
        }
        __syncthreads();

        #pragma unroll
        for (int ks = 0; ks < 8; ks++) {
            const int k0 = ks * 8;
            uint32_t a0 = __float_as_uint(sAt[arow * 68 + k0 + kq]);
            uint32_t a1 = __float_as_uint(sAt[(arow + 8) * 68 + k0 + kq]);
            uint32_t a2 = __float_as_uint(sAt[arow * 68 + k0 + 4 + kq]);
            uint32_t a3 = __float_as_uint(sAt[(arow + 8) * 68 + k0 + 4 + kq]);
            #pragma unroll
            for (int f = 0; f < 4; f++) {
                int n = wd * 32 + f * 8 + (lid >> 2);
                uint32_t b0 = __float_as_uint(sS[(k0 + kq) * 132 + n]);
                uint32_t b1 = __float_as_uint(sS[(k0 + 4 + kq) * 132 + n]);
                mma_tf32(acc[f], a0, a1, a2, a3, b0, b1);
            }
        }
    }

    #pragma unroll
    for (int f = 0; f < 4; f++) {
        int d = wd * 32 + f * 8 + (lid & 3) * 2;
        int q = q0 + wq * 16 + (lid >> 2);
        float* drow = out + ((size_t)(b * NQ + q)) * OUTC + NP + d;
        atomicAdd(drow,     acc[f][0]);
        atomicAdd(drow + 1, acc[f][1]);
        float* drow2 = out + ((size_t)(b * NQ + q + 8)) * OUTC + NP + d;
        atomicAdd(drow2,     acc[f][2]);
        atomicAdd(drow2 + 1, acc[f][3]);
    }
}

// =====================================================================
extern "C" void kernel_launch(void* const* d_in, const int* in_sizes, int n_in,
                              void* d_out, int out_size)
{
    const float* nodes = (const float*)d_in[0];
    const float* poses = (const float*)d_in[1];
    const float* attn  = (const float*)d_in[2];
    const int*   esrc  = (const int*)d_in[3];
    const int*   esnk  = (const int*)d_in[4];
    const float* w1e   = (const float*)d_in[5];
    const float* b1e   = (const float*)d_in[6];
    const float* w2e   = (const float*)d_in[7];
    const float* b2e   = (const float*)d_in[8];
    const float* w1n   = (const float*)d_in[9];
    const float* b1n   = (const float*)d_in[10];
    const float* w2n   = (const float*)d_in[11];
    const float* b2n   = (const float*)d_in[12];
    float* out = (float*)d_out;

    cudaFuncSetAttribute(proj_kernel, cudaFuncAttributeMaxDynamicSharedMemorySize,
                         PROJ_SMEM_BYTES);
    cudaFuncSetAttribute(edge_kernel, cudaFuncAttributeMaxDynamicSharedMemorySize,
                         EDGE_SMEM_BYTES);
    cudaFuncSetAttribute(node_kernel, cudaFuncAttributeMaxDynamicSharedMemorySize,
                         NODE_SMEM_BYTES);

    // copy + fp16 mirror + csr count zero + out init (fused)
    copy_states_kernel<<<(NB * NN * ND / 4 + 255) / 256, 256>>>(nodes, poses, out);

    // CSR chain (hist also zeroes g_incoming)
    csr_hist_kernel<<<(NE + 255) / 256, 256>>>(esnk);
    csr_scan_kernel<<<1, 1024>>>();
    csr_scatter_kernel<<<(NE + 255) / 256, 256>>>(esrc, esnk);
    tile_meta_kernel<<<NTE_B, TEE>>>();

    for (int s = 0; s < 3; s++) {
        proj_kernel<<<148, 512, PROJ_SMEM_BYTES>>>(w1e);
        edge_kernel<<<148, 512, EDGE_SMEM_BYTES>>>(b1e, w2e, b2e);
        node_kernel<<<148, 512, NODE_SMEM_BYTES>>>(w1n, b1n, w2n, b2n);
    }
    extract_kernel<<<dim3(NSPLIT, NQ / 32, NB), 256, EXT_SMEM_FLOATS * 4>>>(attn, out);
}

// round 13
// speedup vs baseline: 1.1008x; 1.0848x over previous
#include <cuda_runtime.h>
#include <cuda_fp16.h>
#include <cstdint>

#define NB 4
#define NN 10000
#define NE 160000
#define NQ 256
#define ND 128
#define NM 64
#define NU 126
#define NH 128
#define NP 7
#define OUTC (NP + ND)   // 135

#define TEE 128                    // edges per edge-tile
#define NTE_B (NE / TEE)           // 1250
#define NTE_TOT (NTE_B * NB)       // 5000

#define NT_NODE_B 157              // ceil(10000/64)
#define NT_NODE_TOT (NT_NODE_B * NB)

#define NPT_B 79                   // ceil(10000/128) proj tiles per batch
#define NPT_TOT (NPT_B * NB)       // 316

// -------- scratch (static device globals: allocation-free) --------
__device__ float g_states[NB * NN * ND];                  // 20.5 MB
__device__ __align__(16) __half g_statesH[NB * NN * ND];  // 10.2 MB fp16 mirror
__device__ float g_incoming[NB * NN * NM];                // 10.2 MB
__device__ __align__(16) __half g_P1[NB * NN * NH];       // src projections
__device__ __align__(16) __half g_P2[NB * NN * NH];       // snk projections
// CSR + tile metadata
__device__ int g_count[NN];
__device__ int g_cur[NN];
__device__ int g_sortedSrc[NE];
__device__ int g_sortedSnk[NE];
__device__ int g_li[NE];               // per-edge local unique-sink index
__device__ int g_uniq[NTE_B * TEE];    // per-tile unique sink list
__device__ int g_ucnt[NTE_B];          // per-tile unique count

// ============================ helpers ============================
__device__ __forceinline__ uint32_t smem_u32(const void* p) {
    uint32_t a;
    asm("{ .reg .u64 t; cvta.to.shared.u64 t, %1; cvt.u32.u64 %0, t; }"
        : "=r"(a) : "l"(p));
    return a;
}
__device__ __forceinline__ uint32_t pack_h2(float a, float b) {
    __half2 h = __floats2half2_rn(a, b);
    return *reinterpret_cast<uint32_t*>(&h);
}
__device__ __forceinline__ void mma_f16(float* c, uint32_t a0, uint32_t a1,
                                        uint32_t a2, uint32_t a3,
                                        uint32_t b0, uint32_t b1) {
    asm volatile(
        "mma.sync.aligned.m16n8k16.row.col.f32.f16.f16.f32 "
        "{%0,%1,%2,%3}, {%4,%5,%6,%7}, {%8,%9}, {%0,%1,%2,%3};"
        : "+f"(c[0]), "+f"(c[1]), "+f"(c[2]), "+f"(c[3])
        : "r"(a0), "r"(a1), "r"(a2), "r"(a3), "r"(b0), "r"(b1));
}
#define CP_ASYNC16(dst, src) \
    asm volatile("cp.async.cg.shared.global [%0], [%1], 16;" \
                 :: "r"(dst), "l"(src) : "memory")
#define CP_COMMIT() asm volatile("cp.async.commit_group;" ::: "memory")
#define CP_WAIT0()  asm volatile("cp.async.wait_group 0;" ::: "memory")

// -------- utility kernels --------
// copy + fp16 mirror + csr count zero + out-pose init (independent ranges)
__global__ void copy_states_kernel(const float* __restrict__ src,
                                   const float* __restrict__ poses,
                                   float* __restrict__ out) {
    int i = blockIdx.x * blockDim.x + threadIdx.x;
    const int n = NB * NN * ND / 4;
    if (i < n) {
        float4 v = reinterpret_cast<const float4*>(src)[i];
        reinterpret_cast<float4*>(g_states)[i] = v;
        __half2* mh = reinterpret_cast<__half2*>(g_statesH);
        mh[2 * i]     = __floats2half2_rn(v.x, v.y);
        mh[2 * i + 1] = __floats2half2_rn(v.z, v.w);
    }
    if (i < NN) g_count[i] = 0;
    if (i < NB * NQ * OUTC) {
        int r = i / OUTC, c = i - r * OUTC;
        out[i] = (c < NP) ? poses[r * NP + c] : 0.f;
    }
}

// -------- CSR build (once per launch; graph static) --------
// hist + fused zero_incoming: grid is exactly 625*256 = 160000 threads
__global__ void csr_hist_kernel(const int* __restrict__ esnk) {
    int i = blockIdx.x * blockDim.x + threadIdx.x;
    float4 z = make_float4(0.f, 0.f, 0.f, 0.f);
    #pragma unroll
    for (int t = 0; t < 4; t++) {
        int j = i + t * 160000;
        if (j < NB * NN * NM / 4)
            reinterpret_cast<float4*>(g_incoming)[j] = z;
    }
    if (i < NE) atomicAdd(&g_count[esnk[i]], 1);
}
__global__ void csr_scan_kernel() {
    __shared__ int part[1024];
    int t = threadIdx.x;
    int beg = t * 10;
    int end = beg + 10 < NN ? beg + 10 : NN;
    int s = 0;
    for (int i = beg; i < end; i++) s += g_count[i];
    part[t] = s;
    __syncthreads();
    for (int d = 1; d < 1024; d <<= 1) {
        int v = (t >= d) ? part[t - d] : 0;
        __syncthreads();
        part[t] += v;
        __syncthreads();
    }
    int base = (t > 0) ? part[t - 1] : 0;
    for (int i = beg; i < end; i++) {
        g_cur[i] = base;
        base += g_count[i];
    }
}
__global__ void csr_scatter_kernel(const int* __restrict__ esrc,
                                   const int* __restrict__ esnk) {
    int i = blockIdx.x * blockDim.x + threadIdx.x;
    if (i < NE) {
        int s = esnk[i];
        int p = atomicAdd(&g_cur[s], 1);
        g_sortedSrc[p] = esrc[i];
        g_sortedSnk[p] = s;
    }
}
__global__ void tile_meta_kernel() {
    __shared__ int fl[TEE];
    int t = blockIdx.x, tid = threadIdx.x;
    int e = t * TEE + tid;
    int s = g_sortedSnk[e];
    int flag = (tid == 0) || (s != g_sortedSnk[e - 1]);
    fl[tid] = flag;
    __syncthreads();
    for (int d = 1; d < TEE; d <<= 1) {
        int v = (tid >= d) ? fl[tid - d] : 0;
        __syncthreads();
        fl[tid] += v;
        __syncthreads();
    }
    int li = fl[tid] - 1;
    g_li[e] = li;
    if (flag) g_uniq[t * TEE + li] = s;
    if (tid == TEE - 1) g_ucnt[t] = fl[tid];
}

// =====================================================================
// Projection kernel (R10 champion version, 256 thr):
// P1 = statesH @ W1top, P2 = statesH @ W1bot (fp16 out)
// smem: PW [0,16384) frags [8 sg][32 nf][32][2]; PA [16384,+2*8704)
// =====================================================================
#define PW 0
#define PA 16384
#define PROJ_SMEM_BYTES ((16384 + 2 * 8704) * 4)   // 135168

__device__ __forceinline__ void proj_issue(uint32_t aBase, int b, int n0, int tid) {
    const __half* stH = g_statesH + (size_t)b * NN * ND;
    #pragma unroll
    for (int t = 0; t < 8; t++) {
        int idx = tid + t * 256;       // 0..2047
        int row = idx >> 4, ch = idx & 15;
        int node = n0 + row;
        if (node >= NN) node = NN - 1;   // clamp; stores are guarded
        uint32_t dst = aBase + row * 272 + ch * 16;
        CP_ASYNC16(dst, stH + (size_t)node * ND + ch * 8);
    }
}

__global__ __launch_bounds__(256, 1) void proj_kernel(
    const float* __restrict__ w1)
{
    extern __shared__ uint32_t su[];
    const int tid = threadIdx.x;
    const int lid = tid & 31;
    const int wid = tid >> 5;
    const int wm = wid >> 1;     // 4 row groups of 32 nodes
    const int wn = wid & 1;      // 2 col halves of 128 h'
    const uint32_t aBase0 = smem_u32(su + PA);

    {
        int T0 = blockIdx.x;
        if (T0 < NPT_TOT) {
            int b0 = T0 / NPT_B;
            proj_issue(aBase0, b0, (T0 - b0 * NPT_B) * 128, tid);
        }
    }
    CP_COMMIT();

    for (int i = tid; i < 8 * 32 * 32; i += 256) {
        int s = i >> 10;
        int f = (i >> 5) & 31;
        int l = i & 31;
        int colg = f * 8 + (l >> 2);
        int krow = s * 16 + (l & 3) * 2;
        int koff = (colg >= 128) ? 128 : 0;
        int col = colg & 127;
        uint2 v;
        v.x = pack_h2(w1[(koff + krow) * NH + col],     w1[(koff + krow + 1) * NH + col]);
        v.y = pack_h2(w1[(koff + krow + 8) * NH + col], w1[(koff + krow + 9) * NH + col]);
        *(uint2*)(su + PW + 2 * i) = v;
    }

    int it = 0;
    for (int T = blockIdx.x; T < NPT_TOT; T += gridDim.x, it++) {
        const int b = T / NPT_B;
        const int n0 = (T - b * NPT_B) * 128;

        CP_WAIT0();
        __syncthreads();

        {
            int Tn = T + gridDim.x;
            if (Tn < NPT_TOT) {
                int bn = Tn / NPT_B;
                proj_issue(aBase0 + ((it + 1) & 1) * 8704 * 4,
                           bn, (Tn - bn * NPT_B) * 128, tid);
            }
        }
        CP_COMMIT();

        const uint32_t* A = su + PA + (it & 1) * 8704;
        #pragma unroll 1
        for (int mf = 0; mf < 2; mf++) {
            float acc[16][4];
            #pragma unroll
            for (int f = 0; f < 16; f++)
                #pragma unroll
                for (int j = 0; j < 4; j++) acc[f][j] = 0.f;

            const int r0 = wm * 32 + mf * 16 + (lid >> 2);
            #pragma unroll
            for (int sg = 0; sg < 8; sg++) {
                const int kw = sg * 8 + (lid & 3);
                uint32_t a0 = A[r0 * 68 + kw];
                uint32_t a1 = A[(r0 + 8) * 68 + kw];
                uint32_t a2 = A[r0 * 68 + kw + 4];
                uint32_t a3 = A[(r0 + 8) * 68 + kw + 4];
                #pragma unroll
                for (int f = 0; f < 16; f++) {
                    uint2 bp = *(const uint2*)(su + PW +
                        ((sg * 32 + wn * 16 + f) * 32 + lid) * 2);
                    mma_f16(acc[f], a0, a1, a2, a3, bp.x, bp.y);
                }
            }
            #pragma unroll
            for (int f = 0; f < 16; f++) {
                const float* c = acc[f];
                int colg = wn * 128 + f * 8 + (lid & 3) * 2;
                __half* P = (colg < 128) ? g_P1 : g_P2;
                int col = colg & 127;
                int node0 = n0 + r0, node1 = n0 + r0 + 8;
                if (node0 < NN)
                    *(uint32_t*)(P + ((size_t)b * NN + node0) * NH + col) =
                        pack_h2(c[0], c[1]);
                if (node1 < NN)
                    *(uint32_t*)(P + ((size_t)b * NN + node1) * NH + col) =
                        pack_h2(c[2], c[3]);
            }
        }
        __syncthreads();
    }
}

// =====================================================================
// Edge kernel (R10 champion, unchanged): gather P1[src] + P2[unique],
// H in registers, GEMM2, segmented scatter. 512 thr, 1 CTA/SM.
// =====================================================================
#define EW2O  0
#define EB2O  4096
#define SLIO  4160
#define SSKO  4416
#define EMSO  4672
#define GP1O  13376
#define GP2O  30784
#define EDGE_SMEM_BYTES (48192 * 4)   // 192768

__device__ __forceinline__ void edge_issue(
    uint32_t gp1Base, uint32_t gp2Base, uint32_t liBase, uint32_t skBase,
    int buf, int t, int b, int tid)
{
    const int eb = t * TEE;
    const char* P1 = (const char*)(g_P1 + (size_t)b * NN * NH);
    const char* P2 = (const char*)(g_P2 + (size_t)b * NN * NH);
    uint32_t g1 = gp1Base + buf * 8704 * 4;
    uint32_t g2 = gp2Base + buf * 8704 * 4;
    #pragma unroll
    for (int i = 0; i < 4; i++) {
        int idx = tid + i * 512;        // 0..2047
        int row = idx >> 4, ch = idx & 15;
        int node = g_sortedSrc[eb + row];
        CP_ASYNC16(g1 + (uint32_t)(row * 272 + ch * 16),
                   P1 + (size_t)node * 256 + ch * 16);
    }
    int uc = g_ucnt[t] * 16;
    for (int i = tid; i < uc; i += 512) {
        int row = i >> 4, ch = i & 15;
        int node = g_uniq[t * TEE + row];
        CP_ASYNC16(g2 + (uint32_t)(row * 272 + ch * 16),
                   P2 + (size_t)node * 256 + ch * 16);
    }
    if (tid < 32)
        CP_ASYNC16(liBase + buf * 512 + tid * 16,
                   (const char*)(g_li + eb) + tid * 16);
    else if (tid < 64)
        CP_ASYNC16(skBase + buf * 512 + (tid - 32) * 16,
                   (const char*)(g_sortedSnk + eb) + (tid - 32) * 16);
}

__global__ __launch_bounds__(512, 1) void edge_kernel(
    const float* __restrict__ b1,
    const float* __restrict__ w2, const float* __restrict__ b2)
{
    extern __shared__ uint32_t su[];
    float* sfB2 = (float*)(su + EB2O);
    int* sLiB = (int*)(su + SLIO);
    int* sSnkB = (int*)(su + SSKO);
    float* sfMSG = (float*)(su + EMSO);

    const int tid = threadIdx.x;
    const int lid = tid & 31;
    const int wid = tid >> 5;          // 0..15
    const int wg  = wid >> 1;          // 8 row groups of 16 edges
    const int wc  = wid & 1;           // column half of NM
    const uint32_t gp1Base = smem_u32(su + GP1O);
    const uint32_t gp2Base = smem_u32(su + GP2O);
    const uint32_t liBase  = smem_u32(su + SLIO);
    const uint32_t skBase  = smem_u32(su + SSKO);

    {
        int T0 = blockIdx.x;
        int b0 = T0 / NTE_B;
        edge_issue(gp1Base, gp2Base, liBase, skBase, 0, T0 - b0 * NTE_B, b0, tid);
    }
    CP_COMMIT();

    for (int i = tid; i < 8 * 8 * 32; i += 512) {
        int s = i >> 8, f = (i >> 5) & 7, l = i & 31;
        int k = s * 16 + (l & 3) * 2, n = f * 8 + (l >> 2);
        uint2 v;
        v.x = pack_h2(w2[k * NM + n],       w2[(k + 1) * NM + n]);
        v.y = pack_h2(w2[(k + 8) * NM + n], w2[(k + 9) * NM + n]);
        *(uint2*)(su + EW2O + 2 * i) = v;
    }
    if (tid < NM) sfB2[tid] = b2[tid];

    __half2 b1r[16];
    #pragma unroll
    for (int t = 0; t < 16; t++) {
        int c = 4 * t + (lid & 3);
        b1r[t] = __floats2half2_rn(b1[2 * c], b1[2 * c + 1]);
    }

    const int arq = wg * 16 + (lid >> 2);
    const __half2 hz = __floats2half2_rn(0.f, 0.f);

    int it = 0;
    for (int T = blockIdx.x; T < NTE_TOT; T += gridDim.x, it++) {
        const int b = T / NTE_B;
        const int cb = it & 1;
        float* inc = g_incoming + (size_t)b * NN * NM;

        CP_WAIT0();
        __syncthreads();

        const uint32_t* G1 = su + GP1O + cb * 8704;
        const uint32_t* G2 = su + GP2O + cb * 8704;
        const int* sLi = sLiB + cb * TEE;
        const int li0 = sLi[arq], li1 = sLi[arq + 8];
        uint32_t hA[8][4];
        #pragma unroll
        for (int sg = 0; sg < 8; sg++) {
            const int c0 = sg * 8 + (lid & 3);
            const int c1 = c0 + 4;
            __half2 v;
            v = __hmax2(__hadd2(__hadd2(*(const __half2*)&G1[arq * 68 + c0],
                                        *(const __half2*)&G2[li0 * 68 + c0]),
                                b1r[2 * sg]), hz);
            hA[sg][0] = *(uint32_t*)&v;
            v = __hmax2(__hadd2(__hadd2(*(const __half2*)&G1[(arq + 8) * 68 + c0],
                                        *(const __half2*)&G2[li1 * 68 + c0]),
                                b1r[2 * sg]), hz);
            hA[sg][1] = *(uint32_t*)&v;
            v = __hmax2(__hadd2(__hadd2(*(const __half2*)&G1[arq * 68 + c1],
                                        *(const __half2*)&G2[li0 * 68 + c1]),
                                b1r[2 * sg + 1]), hz);
            hA[sg][2] = *(uint32_t*)&v;
            v = __hmax2(__hadd2(__hadd2(*(const __half2*)&G1[(arq + 8) * 68 + c1],
                                        *(const __half2*)&G2[li1 * 68 + c1]),
                                b1r[2 * sg + 1]), hz);
            hA[sg][3] = *(uint32_t*)&v;
        }

        {
            int Tn = T + gridDim.x;
            if (Tn < NTE_TOT) {
                int bn = Tn / NTE_B;
                edge_issue(gp1Base, gp2Base, liBase, skBase,
                           cb ^ 1, Tn - bn * NTE_B, bn, tid);
            }
        }
        CP_COMMIT();

        float acc2[4][4];
        #pragma unroll
        for (int f = 0; f < 4; f++)
            #pragma unroll
            for (int j = 0; j < 4; j++) acc2[f][j] = 0.f;

        #pragma unroll
        for (int sg = 0; sg < 8; sg++) {
            #pragma unroll
            for (int f = 0; f < 4; f++) {
                uint2 bp = *(const uint2*)(su + EW2O +
                    ((sg * 8 + wc * 4 + f) * 32 + lid) * 2);
                mma_f16(acc2[f], hA[sg][0], hA[sg][1], hA[sg][2], hA[sg][3],
                        bp.x, bp.y);
            }
        }

        #pragma unroll
        for (int f = 0; f < 4; f++) {
            int m = wc * 32 + f * 8 + 2 * (lid & 3);
            float bb0 = sfB2[m], bb1 = sfB2[m + 1];
            sfMSG[arq * 68 + m]           = acc2[f][0] + bb0;
            sfMSG[arq * 68 + m + 1]       = acc2[f][1] + bb1;
            sfMSG[(arq + 8) * 68 + m]     = acc2[f][2] + bb0;
            sfMSG[(arq + 8) * 68 + m + 1] = acc2[f][3] + bb1;
        }
        __syncthreads();

        {
            const int* sSnk = sSnkB + cb * TEE;
            const int c = tid & 63;
            const int e0s = (tid >> 6) * 16;
            float part = 0.f;
            int cur = sSnk[e0s];
            #pragma unroll
            for (int j = 0; j < 16; j++) {
                part += sfMSG[(e0s + j) * 68 + c];
                int nxt = (j < 15) ? sSnk[e0s + j + 1] : -1;
                if (nxt != cur) {
                    atomicAdd(inc + (size_t)cur * NM + c, part);
                    part = 0.f;
                    cur = nxt;
                }
            }
        }
    }
}

// =====================================================================
// Node kernel (R10 champion, unchanged): 256 thr, full-tile cp.async
// pipeline, zeroes incoming, maintains fp16 mirror.
// =====================================================================
#define NW1 0
#define NW2 12288
#define NB1 20480
#define NB2 20608
#define NHS 20736
#define NAB 25088
#define NODE_SMEM_BYTES (46592 * 4)   // 186368

__device__ __forceinline__ void node_issue(uint32_t aBase, int buf, int b,
                                           int n0, int tid) {
    const char* stH = (const char*)(g_statesH + (size_t)b * NN * ND);
    const char* inc = (const char*)(g_incoming + (size_t)b * NN * NM);
    uint32_t abuf = aBase + buf * 10752 * 4;
    uint32_t ibuf = abuf + 6400 * 4;
    #pragma unroll
    for (int i = 0; i < 4; i++) {
        int idx = tid + i * 256;   // 0..1023
        int row = idx >> 4, ch = idx & 15;
        int node = n0 + row;
        if (node < NN) {
            CP_ASYNC16(abuf + (uint32_t)(row * 400 + 128 + ch * 16),
                       stH + (size_t)node * 256 + ch * 16);
            CP_ASYNC16(ibuf + (uint32_t)(row * 272 + ch * 16),
                       inc + (size_t)node * 256 + ch * 16);
        }
    }
}

__global__ __launch_bounds__(256, 1) void node_kernel(
    const float* __restrict__ w1, const float* __restrict__ b1,
    const float* __restrict__ w2, const float* __restrict__ b2)
{
    extern __shared__ uint32_t su[];
    float* sfB1 = (float*)(su + NB1);
    float* sfB2 = (float*)(su + NB2);

    const int tid = threadIdx.x;
    const int lid = tid & 31;
    const int wid = tid >> 5;
    const int wr = wid & 3;
    const int wc = wid >> 2;
    const uint32_t aBase = smem_u32(su + NAB);

    {
        int T0 = blockIdx.x;
        if (T0 < NT_NODE_TOT) {
            int b0 = T0 / NT_NODE_B;
            node_issue(aBase, 0, b0, (T0 - b0 * NT_NODE_B) * 64, tid);
        }
    }
    CP_COMMIT();

    for (int i = tid; i < 12 * 16 * 32; i += 256) {
        int s = i >> 9, f = (i >> 5) & 15, l = i & 31;
        int k = s * 16 + (l & 3) * 2, n = f * 8 + (l >> 2);
        uint2 v;
        v.x = pack_h2(w1[k * NH + n],       w1[(k + 1) * NH + n]);
        v.y = pack_h2(w1[(k + 8) * NH + n], w1[(k + 9) * NH + n]);
        *(uint2*)(su + NW1 + 2 * i) = v;
    }
    for (int i = tid; i < 8 * 16 * 32; i += 256) {
        int s = i >> 9, f = (i >> 5) & 15, l = i & 31;
        int k = s * 16 + (l & 3) * 2, n = f * 8 + (l >> 2);
        uint2 v;
        if (n < NU) {
            v.x = pack_h2(w2[k * NU + n],       w2[(k + 1) * NU + n]);
            v.y = pack_h2(w2[(k + 8) * NU + n], w2[(k + 9) * NU + n]);
        } else v.x = v.y = 0u;
        *(uint2*)(su + NW2 + 2 * i) = v;
    }
    if (tid < NH) sfB1[tid] = b1[tid];
    if (tid < 128) sfB2[tid] = (tid < NU) ? b2[tid] : 0.f;

    const int ar = wr * 16 + (lid >> 2);

    int it = 0;
    for (int T = blockIdx.x; T < NT_NODE_TOT; T += gridDim.x, it++) {
        const int b = T / NT_NODE_B;
        const int n0 = (T - b * NT_NODE_B) * 64;
        const int cb = it & 1;
        float* st = g_states + (size_t)b * NN * ND;
        __half* stH = g_statesH + (size_t)b * NN * ND;
        float* incF = g_incoming + (size_t)b * NN * NM;

        CP_WAIT0();
        __syncthreads();

        {
            uint32_t* A = su + NAB + cb * 10752;
            const uint32_t* INC = A + 6400;
            #pragma unroll
            for (int t = 0; t < 8; t++) {
                int idx = tid + t * 256;
                int row = idx >> 5, c = idx & 31;
                const float* f2 = (const float*)&INC[row * 68 + 2 * c];
                A[row * 100 + c] = pack_h2(f2[0], f2[1]);
            }
            float4 z4 = make_float4(0.f, 0.f, 0.f, 0.f);
            #pragma unroll
            for (int t = 0; t < 4; t++) {
                int idx = tid + t * 256;
                int row = idx >> 4, q = idx & 15;
                int node = n0 + row;
                if (node < NN)
                    *(float4*)(incF + (size_t)node * NM + q * 4) = z4;
            }
        }
        __syncthreads();

        {
            int Tn = T + gridDim.x;
            if (Tn < NT_NODE_TOT) {
                int bn = Tn / NT_NODE_B;
                node_issue(aBase, cb ^ 1, bn, (Tn - bn * NT_NODE_B) * 64, tid);
            }
        }
        CP_COMMIT();

        const uint32_t* A = su + NAB + cb * 10752;
        float acc[8][4];
        #pragma unroll
        for (int f = 0; f < 8; f++)
            #pragma unroll
            for (int j = 0; j < 4; j++) acc[f][j] = 0.f;

        #pragma unroll 4
        for (int sg = 0; sg < 12; sg++) {
            const int kw = sg * 8 + (lid & 3);
            uint32_t a0 = A[ar * 100 + kw];
            uint32_t a1 = A[(ar + 8) * 100 + kw];
            uint32_t a2 = A[ar * 100 + kw + 4];
            uint32_t a3 = A[(ar + 8) * 100 + kw + 4];
            #pragma unroll
            for (int f = 0; f < 8; f++) {
                uint2 bp = *(const uint2*)(su + NW1 +
                    ((sg * 16 + wc * 8 + f) * 32 + lid) * 2);
                mma_f16(acc[f], a0, a1, a2, a3, bp.x, bp.y);
            }
        }

        #pragma unroll
        for (int f = 0; f < 8; f++) {
            int nn0 = wc * 64 + f * 8 + 2 * (lid & 3);
            float bb0 = sfB1[nn0], bb1 = sfB1[nn0 + 1];
            int wcol = wc * 32 + f * 4 + (lid & 3);
            su[NHS + ar * 68 + wcol] =
                pack_h2(fmaxf(acc[f][0] + bb0, 0.f), fmaxf(acc[f][1] + bb1, 0.f));
            su[NHS + (ar + 8) * 68 + wcol] =
                pack_h2(fmaxf(acc[f][2] + bb0, 0.f), fmaxf(acc[f][3] + bb1, 0.f));
        }
        __syncthreads();

        float acc2[8][4];
        #pragma unroll
        for (int f = 0; f < 8; f++)
            #pragma unroll
            for (int j = 0; j < 4; j++) acc2[f][j] = 0.f;

        #pragma unroll 2
        for (int ks = 0; ks < 8; ks++) {
            const int kw = ks * 8 + (lid & 3);
            uint32_t a0 = su[NHS + ar * 68 + kw];
            uint32_t a1 = su[NHS + (ar + 8) * 68 + kw];
            uint32_t a2 = su[NHS + ar * 68 + kw + 4];
            uint32_t a3 = su[NHS + (ar + 8) * 68 + kw + 4];
            #pragma unroll
            for (int f = 0; f < 8; f++) {
                uint2 bp = *(const uint2*)(su + NW2 +
                    ((ks * 16 + wc * 8 + f) * 32 + lid) * 2);
                mma_f16(acc2[f], a0, a1, a2, a3, bp.x, bp.y);
            }
        }

        {
            const int node0 = n0 + ar, node1 = n0 + ar + 8;
            #pragma unroll
            for (int f = 0; f < 8; f++) {
                int cc = wc * 64 + f * 8 + 2 * (lid & 3);
                float bb0 = sfB2[cc], bb1 = sfB2[cc + 1];
                if (cc < NU) {
                    if (node0 < NN) {
                        float* d = st + (size_t)node0 * ND + 2;
                        float nv0 = d[cc] + acc2[f][0] + bb0;
                        float nv1 = d[cc + 1] + acc2[f][1] + bb1;
                        d[cc] = nv0; d[cc + 1] = nv1;
                        *(__half2*)(stH + (size_t)node0 * ND + 2 + cc) =
                            __floats2half2_rn(nv0, nv1);
                    }
                    if (node1 < NN) {
                        float* d = st + (size_t)node1 * ND + 2;
                        float nv0 = d[cc] + acc2[f][2] + bb0;
                        float nv1 = d[cc + 1] + acc2[f][3] + bb1;
                        d[cc] = nv0; d[cc + 1] = nv1;
                        *(__half2*)(stH + (size_t)node1 * ND + 2 + cc) =
                            __floats2half2_rn(nv0, nv1);
                    }
                }
            }
        }
    }
}

// =====================================================================
// Readout: fp16 mma m16n8k16, reads g_statesH mirror + attn scaled by 1024.
// CTA = 32 q x 128 d, split-K over 8 node ranges.
// smem (u32): sAt [32 q][36] (attn fp16 pairs), sS [64 n][68] (states fp16)
// B frags via ldmatrix.x4.trans.b16 from row-major sS.
// =====================================================================
#define EXT_SAT 0
#define EXT_SS  1152
#define EXT_SMEM_U32 (1152 + 4352)   // 5504 u32 = 22016 B
#define NSPLIT 8
#define NCHUNK (NN / NSPLIT)   // 1250
#define ATT_SCALE 1024.0f
#define ATT_INV   0.0009765625f

__global__ __launch_bounds__(256) void extract_kernel(
    const float* __restrict__ attn, float* __restrict__ out)
{
    extern __shared__ uint32_t su[];
    const int tid = threadIdx.x;
    const int lid = tid & 31;
    const int wid = tid >> 5;
    const int wq = wid & 1;       // q half (16 rows)
    const int wd = wid >> 1;      // d quarter (32 cols)
    const int b = blockIdx.z, qt = blockIdx.y, ns = blockIdx.x;
    const int q0 = qt * 32;
    const int nbeg = ns * NCHUNK;
    const int nend = nbeg + NCHUNK;
    const __half* stH = g_statesH + (size_t)b * NN * ND;
    const float* at = attn + ((size_t)b * NQ + q0) * NN;
    const uint32_t ssBase = smem_u32(su + EXT_SS);

    float acc[4][4];
    #pragma unroll
    for (int f = 0; f < 4; f++)
        #pragma unroll
        for (int j = 0; j < 4; j++) acc[f][j] = 0.f;

    const int arow = wq * 16 + (lid >> 2);
    // ldmatrix lane address precompute (row within 16-k block, col group)
    const int lm_km = (lid >> 3) & 1;          // k half (0/1)
    const int lm_ng = lid >> 4;                // n8 group (0/1)
    const int lm_r  = lid & 7;                 // row within 8

    for (int n0 = nbeg; n0 < nend; n0 += 64) {
        __syncthreads();
        // stage attn (fp16, x1024): 32 q x 32 u32
        #pragma unroll
        for (int t = 0; t < 4; t++) {
            int idx = tid + t * 256;
            int q = idx >> 5, c = idx & 31;
            int n = n0 + 2 * c;
            float vx = 0.f, vy = 0.f;
            if (n + 1 < nend) {
                float2 v = *(const float2*)&at[(size_t)q * NN + n];
                vx = v.x; vy = v.y;
            } else if (n < nend) {
                vx = at[(size_t)q * NN + n];
            }
            su[EXT_SAT + q * 36 + c] = pack_h2(vx * ATT_SCALE, vy * ATT_SCALE);
        }
        // stage states (fp16 mirror, direct u32 copy): 64 n x 64 u32
        #pragma unroll
        for (int t = 0; t < 16; t++) {
            int idx = tid + t * 256;
            int row = idx >> 6, c = idx & 63;
            int n = n0 + row;
            su[EXT_SS + row * 68 + c] =
                (n < nend) ? ((const uint32_t*)(stH + (size_t)n * ND))[c] : 0u;
        }
        __syncthreads();

        #pragma unroll
        for (int sg = 0; sg < 4; sg++) {       // 4 x k16 = 64 n
            const int kw = sg * 8 + (lid & 3);
            uint32_t a0 = su[EXT_SAT + arow * 36 + kw];
            uint32_t a1 = su[EXT_SAT + (arow + 8) * 36 + kw];
            uint32_t a2 = su[EXT_SAT + arow * 36 + kw + 4];
            uint32_t a3 = su[EXT_SAT + (arow + 8) * 36 + kw + 4];
            #pragma unroll
            for (int g = 0; g < 2; g++) {      // two n16 groups -> 4 n8 frags
                int nb = wd * 32 + g * 16;     // halves col base
                uint32_t addr = ssBase +
                    (uint32_t)((sg * 16 + lm_km * 8 + lm_r) * 272 +
                               (nb + lm_ng * 8) * 2);
                uint32_t r0, r1, r2, r3;
                asm volatile(
                    "ldmatrix.sync.aligned.m8n8.x4.trans.shared.b16 "
                    "{%0,%1,%2,%3}, [%4];"
                    : "=r"(r0), "=r"(r1), "=r"(r2), "=r"(r3) : "r"(addr));
                mma_f16(acc[2 * g],     a0, a1, a2, a3, r0, r1);
                mma_f16(acc[2 * g + 1], a0, a1, a2, a3, r2, r3);
            }
        }
    }

    #pragma unroll
    for (int f = 0; f < 4; f++) {
        int d = wd * 32 + f * 8 + (lid & 3) * 2;
        int q = q0 + wq * 16 + (lid >> 2);
        float* drow = out + ((size_t)(b * NQ + q)) * OUTC + NP + d;
        atomicAdd(drow,     acc[f][0] * ATT_INV);
        atomicAdd(drow + 1, acc[f][1] * ATT_INV);
        float* drow2 = out + ((size_t)(b * NQ + q + 8)) * OUTC + NP + d;
        atomicAdd(drow2,     acc[f][2] * ATT_INV);
        atomicAdd(drow2 + 1, acc[f][3] * ATT_INV);
    }
}

// =====================================================================
extern "C" void kernel_launch(void* const* d_in, const int* in_sizes, int n_in,
                              void* d_out, int out_size)
{
    const float* nodes = (const float*)d_in[0];
    const float* poses = (const float*)d_in[1];
    const float* attn  = (const float*)d_in[2];
    const int*   esrc  = (const int*)d_in[3];
    const int*   esnk  = (const int*)d_in[4];
    const float* w1e   = (const float*)d_in[5];
    const float* b1e   = (const float*)d_in[6];
    const float* w2e   = (const float*)d_in[7];
    const float* b2e   = (const float*)d_in[8];
    const float* w1n   = (const float*)d_in[9];
    const float* b1n   = (const float*)d_in[10];
    const float* w2n   = (const float*)d_in[11];
    const float* b2n   = (const float*)d_in[12];
    float* out = (float*)d_out;

    cudaFuncSetAttribute(proj_kernel, cudaFuncAttributeMaxDynamicSharedMemorySize,
                         PROJ_SMEM_BYTES);
    cudaFuncSetAttribute(edge_kernel, cudaFuncAttributeMaxDynamicSharedMemorySize,
                         EDGE_SMEM_BYTES);
    cudaFuncSetAttribute(node_kernel, cudaFuncAttributeMaxDynamicSharedMemorySize,
                         NODE_SMEM_BYTES);

    // copy + fp16 mirror + csr count zero + out init (fused)
    copy_states_kernel<<<(NB * NN * ND / 4 + 255) / 256, 256>>>(nodes, poses, out);

    // CSR chain (hist also zeroes g_incoming)
    csr_hist_kernel<<<(NE + 255) / 256, 256>>>(esnk);
    csr_scan_kernel<<<1, 1024>>>();
    csr_scatter_kernel<<<(NE + 255) / 256, 256>>>(esrc, esnk);
    tile_meta_kernel<<<NTE_B, TEE>>>();

    for (int s = 0; s < 3; s++) {
        proj_kernel<<<148, 256, PROJ_SMEM_BYTES>>>(w1e);
        edge_kernel<<<148, 512, EDGE_SMEM_BYTES>>>(b1e, w2e, b2e);
        node_kernel<<<148, 256, NODE_SMEM_BYTES>>>(w1n, b1n, w2n, b2n);
    }
    extract_kernel<<<dim3(NSPLIT, NQ / 32, NB), 256, EXT_SMEM_U32 * 4>>>(attn, out);
}

// round 15
// speedup vs baseline: 1.1169x; 1.0146x over previous
#include <cuda_runtime.h>
#include <cuda_fp16.h>
#include <cstdint>

#define NB 4
#define NN 10000
#define NE 160000
#define NQ 256
#define ND 128
#define NM 64
#define NU 126
#define NH 128
#define NP 7
#define OUTC (NP + ND)   // 135

#define TEE 128                    // edges per edge-tile
#define NTE_B (NE / TEE)           // 1250
#define NTE_TOT (NTE_B * NB)       // 5000

#define NT_NODE_B 157              // ceil(10000/64)
#define NT_NODE_TOT (NT_NODE_B * NB)

#define NPT_B 79                   // ceil(10000/128) proj tiles per batch
#define NPT_TOT (NPT_B * NB)       // 316

// -------- scratch (static device globals: allocation-free) --------
__device__ float g_states[NB * NN * ND];                  // 20.5 MB
__device__ __align__(16) __half g_statesH[NB * NN * ND];  // 10.2 MB fp16 mirror
__device__ __align__(16) __half g_incomingH[NB * NN * NM];// 5.1 MB fp16 accumulator
__device__ __align__(16) __half g_P1[NB * NN * NH];       // src projections
__device__ __align__(16) __half g_P2[NB * NN * NH];       // snk projections
// CSR + tile metadata
__device__ int g_count[NN];
__device__ int g_cur[NN];
__device__ int g_sortedSrc[NE];
__device__ int g_sortedSnk[NE];
__device__ int g_li[NE];               // per-edge local unique-sink index
__device__ int g_uniq[NTE_B * TEE];    // per-tile unique sink list
__device__ int g_ucnt[NTE_B];          // per-tile unique count

// ============================ helpers ============================
__device__ __forceinline__ uint32_t smem_u32(const void* p) {
    uint32_t a;
    asm("{ .reg .u64 t; cvta.to.shared.u64 t, %1; cvt.u32.u64 %0, t; }"
        : "=r"(a) : "l"(p));
    return a;
}
__device__ __forceinline__ uint32_t pack_h2(float a, float b) {
    __half2 h = __floats2half2_rn(a, b);
    return *reinterpret_cast<uint32_t*>(&h);
}
__device__ __forceinline__ void mma_f16(float* c, uint32_t a0, uint32_t a1,
                                        uint32_t a2, uint32_t a3,
                                        uint32_t b0, uint32_t b1) {
    asm volatile(
        "mma.sync.aligned.m16n8k16.row.col.f32.f16.f16.f32 "
        "{%0,%1,%2,%3}, {%4,%5,%6,%7}, {%8,%9}, {%0,%1,%2,%3};"
        : "+f"(c[0]), "+f"(c[1]), "+f"(c[2]), "+f"(c[3])
        : "r"(a0), "r"(a1), "r"(a2), "r"(a3), "r"(b0), "r"(b1));
}
#define CP_ASYNC16(dst, src) \
    asm volatile("cp.async.cg.shared.global [%0], [%1], 16;" \
                 :: "r"(dst), "l"(src) : "memory")
#define CP_COMMIT() asm volatile("cp.async.commit_group;" ::: "memory")
#define CP_WAIT0()  asm volatile("cp.async.wait_group 0;" ::: "memory")

// -------- utility kernels --------
// copy + fp16 mirror + csr count zero + out-pose init (independent ranges)
__global__ void copy_states_kernel(const float* __restrict__ src,
                                   const float* __restrict__ poses,
                                   float* __restrict__ out) {
    int i = blockIdx.x * blockDim.x + threadIdx.x;
    const int n = NB * NN * ND / 4;
    if (i < n) {
        float4 v = reinterpret_cast<const float4*>(src)[i];
        reinterpret_cast<float4*>(g_states)[i] = v;
        __half2* mh = reinterpret_cast<__half2*>(g_statesH);
        mh[2 * i]     = __floats2half2_rn(v.x, v.y);
        mh[2 * i + 1] = __floats2half2_rn(v.z, v.w);
    }
    if (i < NN) g_count[i] = 0;
    if (i < NB * NQ * OUTC) {
        int r = i / OUTC, c = i - r * OUTC;
        out[i] = (c < NP) ? poses[r * NP + c] : 0.f;
    }
}

// -------- CSR build (once per launch; graph static) --------
// hist + fused zero of fp16 incoming: 160000 threads; 320000 float4 to zero
__global__ void csr_hist_kernel(const int* __restrict__ esnk) {
    int i = blockIdx.x * blockDim.x + threadIdx.x;
    float4 z = make_float4(0.f, 0.f, 0.f, 0.f);
    #pragma unroll
    for (int t = 0; t < 2; t++) {
        int j = i + t * 160000;
        if (j < NB * NN * NM * 2 / 16)
            reinterpret_cast<float4*>(g_incomingH)[j] = z;
    }
    if (i < NE) atomicAdd(&g_count[esnk[i]], 1);
}
__global__ void csr_scan_kernel() {
    __shared__ int part[1024];
    int t = threadIdx.x;
    int beg = t * 10;
    int end = beg + 10 < NN ? beg + 10 : NN;
    int s = 0;
    for (int i = beg; i < end; i++) s += g_count[i];
    part[t] = s;
    __syncthreads();
    for (int d = 1; d < 1024; d <<= 1) {
        int v = (t >= d) ? part[t - d] : 0;
        __syncthreads();
        part[t] += v;
        __syncthreads();
    }
    int base = (t > 0) ? part[t - 1] : 0;
    for (int i = beg; i < end; i++) {
        g_cur[i] = base;
        base += g_count[i];
    }
}
__global__ void csr_scatter_kernel(const int* __restrict__ esrc,
                                   const int* __restrict__ esnk) {
    int i = blockIdx.x * blockDim.x + threadIdx.x;
    if (i < NE) {
        int s = esnk[i];
        int p = atomicAdd(&g_cur[s], 1);
        g_sortedSrc[p] = esrc[i];
        g_sortedSnk[p] = s;
    }
}
__global__ void tile_meta_kernel() {
    __shared__ int fl[TEE];
    int t = blockIdx.x, tid = threadIdx.x;
    int e = t * TEE + tid;
    int s = g_sortedSnk[e];
    int flag = (tid == 0) || (s != g_sortedSnk[e - 1]);
    fl[tid] = flag;
    __syncthreads();
    for (int d = 1; d < TEE; d <<= 1) {
        int v = (tid >= d) ? fl[tid - d] : 0;
        __syncthreads();
        fl[tid] += v;
        __syncthreads();
    }
    int li = fl[tid] - 1;
    g_li[e] = li;
    if (flag) g_uniq[t * TEE + li] = s;
    if (tid == TEE - 1) g_ucnt[t] = fl[tid];
}

// =====================================================================
// Projection kernel (champion version, 256 thr):
// P1 = statesH @ W1top, P2 = statesH @ W1bot (fp16 out)
// =====================================================================
#define PW 0
#define PA 16384
#define PROJ_SMEM_BYTES ((16384 + 2 * 8704) * 4)   // 135168

__device__ __forceinline__ void proj_issue(uint32_t aBase, int b, int n0, int tid) {
    const __half* stH = g_statesH + (size_t)b * NN * ND;
    #pragma unroll
    for (int t = 0; t < 8; t++) {
        int idx = tid + t * 256;       // 0..2047
        int row = idx >> 4, ch = idx & 15;
        int node = n0 + row;
        if (node >= NN) node = NN - 1;   // clamp; stores are guarded
        uint32_t dst = aBase + row * 272 + ch * 16;
        CP_ASYNC16(dst, stH + (size_t)node * ND + ch * 8);
    }
}

__global__ __launch_bounds__(256, 1) void proj_kernel(
    const float* __restrict__ w1)
{
    extern __shared__ uint32_t su[];
    const int tid = threadIdx.x;
    const int lid = tid & 31;
    const int wid = tid >> 5;
    const int wm = wid >> 1;     // 4 row groups of 32 nodes
    const int wn = wid & 1;      // 2 col halves of 128 h'
    const uint32_t aBase0 = smem_u32(su + PA);

    {
        int T0 = blockIdx.x;
        if (T0 < NPT_TOT) {
            int b0 = T0 / NPT_B;
            proj_issue(aBase0, b0, (T0 - b0 * NPT_B) * 128, tid);
        }
    }
    CP_COMMIT();

    for (int i = tid; i < 8 * 32 * 32; i += 256) {
        int s = i >> 10;
        int f = (i >> 5) & 31;
        int l = i & 31;
        int colg = f * 8 + (l >> 2);
        int krow = s * 16 + (l & 3) * 2;
        int koff = (colg >= 128) ? 128 : 0;
        int col = colg & 127;
        uint2 v;
        v.x = pack_h2(w1[(koff + krow) * NH + col],     w1[(koff + krow + 1) * NH + col]);
        v.y = pack_h2(w1[(koff + krow + 8) * NH + col], w1[(koff + krow + 9) * NH + col]);
        *(uint2*)(su + PW + 2 * i) = v;
    }

    int it = 0;
    for (int T = blockIdx.x; T < NPT_TOT; T += gridDim.x, it++) {
        const int b = T / NPT_B;
        const int n0 = (T - b * NPT_B) * 128;

        CP_WAIT0();
        __syncthreads();

        {
            int Tn = T + gridDim.x;
            if (Tn < NPT_TOT) {
                int bn = Tn / NPT_B;
                proj_issue(aBase0 + ((it + 1) & 1) * 8704 * 4,
                           bn, (Tn - bn * NPT_B) * 128, tid);
            }
        }
        CP_COMMIT();

        const uint32_t* A = su + PA + (it & 1) * 8704;
        #pragma unroll 1
        for (int mf = 0; mf < 2; mf++) {
            float acc[16][4];
            #pragma unroll
            for (int f = 0; f < 16; f++)
                #pragma unroll
                for (int j = 0; j < 4; j++) acc[f][j] = 0.f;

            const int r0 = wm * 32 + mf * 16 + (lid >> 2);
            #pragma unroll
            for (int sg = 0; sg < 8; sg++) {
                const int kw = sg * 8 + (lid & 3);
                uint32_t a0 = A[r0 * 68 + kw];
                uint32_t a1 = A[(r0 + 8) * 68 + kw];
                uint32_t a2 = A[r0 * 68 + kw + 4];
                uint32_t a3 = A[(r0 + 8) * 68 + kw + 4];
                #pragma unroll
                for (int f = 0; f < 16; f++) {
                    uint2 bp = *(const uint2*)(su + PW +
                        ((sg * 32 + wn * 16 + f) * 32 + lid) * 2);
                    mma_f16(acc[f], a0, a1, a2, a3, bp.x, bp.y);
                }
            }
            #pragma unroll
            for (int f = 0; f < 16; f++) {
                const float* c = acc[f];
                int colg = wn * 128 + f * 8 + (lid & 3) * 2;
                __half* P = (colg < 128) ? g_P1 : g_P2;
                int col = colg & 127;
                int node0 = n0 + r0, node1 = n0 + r0 + 8;
                if (node0 < NN)
                    *(uint32_t*)(P + ((size_t)b * NN + node0) * NH + col) =
                        pack_h2(c[0], c[1]);
                if (node1 < NN)
                    *(uint32_t*)(P + ((size_t)b * NN + node1) * NH + col) =
                        pack_h2(c[2], c[3]);
            }
        }
        __syncthreads();
    }
}

// =====================================================================
// Edge kernel: gather P1[src] + P2[unique], H in registers, GEMM2,
// segmented scatter with f16x2 atomics. 512 thr, 1 CTA/SM.
// =====================================================================
#define EW2O  0
#define EB2O  4096
#define SLIO  4160
#define SSKO  4416
#define EMSO  4672
#define GP1O  13376
#define GP2O  30784
#define EDGE_SMEM_BYTES (48192 * 4)   // 192768

__device__ __forceinline__ void edge_issue(
    uint32_t gp1Base, uint32_t gp2Base, uint32_t liBase, uint32_t skBase,
    int buf, int t, int b, int tid)
{
    const int eb = t * TEE;
    const char* P1 = (const char*)(g_P1 + (size_t)b * NN * NH);
    const char* P2 = (const char*)(g_P2 + (size_t)b * NN * NH);
    uint32_t g1 = gp1Base + buf * 8704 * 4;
    uint32_t g2 = gp2Base + buf * 8704 * 4;
    #pragma unroll
    for (int i = 0; i < 4; i++) {
        int idx = tid + i * 512;        // 0..2047
        int row = idx >> 4, ch = idx & 15;
        int node = g_sortedSrc[eb + row];
        CP_ASYNC16(g1 + (uint32_t)(row * 272 + ch * 16),
                   P1 + (size_t)node * 256 + ch * 16);
    }
    int uc = g_ucnt[t] * 16;
    for (int i = tid; i < uc; i += 512) {
        int row = i >> 4, ch = i & 15;
        int node = g_uniq[t * TEE + row];
        CP_ASYNC16(g2 + (uint32_t)(row * 272 + ch * 16),
                   P2 + (size_t)node * 256 + ch * 16);
    }
    if (tid < 32)
        CP_ASYNC16(liBase + buf * 512 + tid * 16,
                   (const char*)(g_li + eb) + tid * 16);
    else if (tid < 64)
        CP_ASYNC16(skBase + buf * 512 + (tid - 32) * 16,
                   (const char*)(g_sortedSnk + eb) + (tid - 32) * 16);
}

__global__ __launch_bounds__(512, 1) void edge_kernel(
    const float* __restrict__ b1,
    const float* __restrict__ w2, const float* __restrict__ b2)
{
    extern __shared__ uint32_t su[];
    float* sfB2 = (float*)(su + EB2O);
    int* sLiB = (int*)(su + SLIO);
    int* sSnkB = (int*)(su + SSKO);
    float* sfMSG = (float*)(su + EMSO);

    const int tid = threadIdx.x;
    const int lid = tid & 31;
    const int wid = tid >> 5;          // 0..15
    const int wg  = wid >> 1;          // 8 row groups of 16 edges
    const int wc  = wid & 1;           // column half of NM
    const uint32_t gp1Base = smem_u32(su + GP1O);
    const uint32_t gp2Base = smem_u32(su + GP2O);
    const uint32_t liBase  = smem_u32(su + SLIO);
    const uint32_t skBase  = smem_u32(su + SSKO);

    {
        int T0 = blockIdx.x;
        int b0 = T0 / NTE_B;
        edge_issue(gp1Base, gp2Base, liBase, skBase, 0, T0 - b0 * NTE_B, b0, tid);
    }
    CP_COMMIT();

    for (int i = tid; i < 8 * 8 * 32; i += 512) {
        int s = i >> 8, f = (i >> 5) & 7, l = i & 31;
        int k = s * 16 + (l & 3) * 2, n = f * 8 + (l >> 2);
        uint2 v;
        v.x = pack_h2(w2[k * NM + n],       w2[(k + 1) * NM + n]);
        v.y = pack_h2(w2[(k + 8) * NM + n], w2[(k + 9) * NM + n]);
        *(uint2*)(su + EW2O + 2 * i) = v;
    }
    if (tid < NM) sfB2[tid] = b2[tid];

    __half2 b1r[16];
    #pragma unroll
    for (int t = 0; t < 16; t++) {
        int c = 4 * t + (lid & 3);
        b1r[t] = __floats2half2_rn(b1[2 * c], b1[2 * c + 1]);
    }

    const int arq = wg * 16 + (lid >> 2);
    const __half2 hz = __floats2half2_rn(0.f, 0.f);

    int it = 0;
    for (int T = blockIdx.x; T < NTE_TOT; T += gridDim.x, it++) {
        const int b = T / NTE_B;
        const int cb = it & 1;
        __half* inc = g_incomingH + (size_t)b * NN * NM;

        CP_WAIT0();
        __syncthreads();

        const uint32_t* G1 = su + GP1O + cb * 8704;
        const uint32_t* G2 = su + GP2O + cb * 8704;
        const int* sLi = sLiB + cb * TEE;
        const int li0 = sLi[arq], li1 = sLi[arq + 8];
        uint32_t hA[8][4];
        #pragma unroll
        for (int sg = 0; sg < 8; sg++) {
            const int c0 = sg * 8 + (lid & 3);
            const int c1 = c0 + 4;
            __half2 v;
            v = __hmax2(__hadd2(__hadd2(*(const __half2*)&G1[arq * 68 + c0],
                                        *(const __half2*)&G2[li0 * 68 + c0]),
                                b1r[2 * sg]), hz);
            hA[sg][0] = *(uint32_t*)&v;
            v = __hmax2(__hadd2(__hadd2(*(const __half2*)&G1[(arq + 8) * 68 + c0],
                                        *(const __half2*)&G2[li1 * 68 + c0]),
                                b1r[2 * sg]), hz);
            hA[sg][1] = *(uint32_t*)&v;
            v = __hmax2(__hadd2(__hadd2(*(const __half2*)&G1[arq * 68 + c1],
                                        *(const __half2*)&G2[li0 * 68 + c1]),
                                b1r[2 * sg + 1]), hz);
            hA[sg][2] = *(uint32_t*)&v;
            v = __hmax2(__hadd2(__hadd2(*(const __half2*)&G1[(arq + 8) * 68 + c1],
                                        *(const __half2*)&G2[li1 * 68 + c1]),
                                b1r[2 * sg + 1]), hz);
            hA[sg][3] = *(uint32_t*)&v;
        }

        {
            int Tn = T + gridDim.x;
            if (Tn < NTE_TOT) {
                int bn = Tn / NTE_B;
                edge_issue(gp1Base, gp2Base, liBase, skBase,
                           cb ^ 1, Tn - bn * NTE_B, bn, tid);
            }
        }
        CP_COMMIT();

        float acc2[4][4];
        #pragma unroll
        for (int f = 0; f < 4; f++)
            #pragma unroll
            for (int j = 0; j < 4; j++) acc2[f][j] = 0.f;

        #pragma unroll
        for (int sg = 0; sg < 8; sg++) {
            #pragma unroll
            for (int f = 0; f < 4; f++) {
                uint2 bp = *(const uint2*)(su + EW2O +
                    ((sg * 8 + wc * 4 + f) * 32 + lid) * 2);
                mma_f16(acc2[f], hA[sg][0], hA[sg][1], hA[sg][2], hA[sg][3],
                        bp.x, bp.y);
            }
        }

        #pragma unroll
        for (int f = 0; f < 4; f++) {
            int m = wc * 32 + f * 8 + 2 * (lid & 3);
            float bb0 = sfB2[m], bb1 = sfB2[m + 1];
            sfMSG[arq * 68 + m]           = acc2[f][0] + bb0;
            sfMSG[arq * 68 + m + 1]       = acc2[f][1] + bb1;
            sfMSG[(arq + 8) * 68 + m]     = acc2[f][2] + bb0;
            sfMSG[(arq + 8) * 68 + m + 1] = acc2[f][3] + bb1;
        }
        __syncthreads();

        // segmented reduction over sorted sinks; f16x2 atomics
        {
            const int* sSnk = sSnkB + cb * TEE;
            const int c2 = tid & 31;        // half2 channel (2 floats)
            const int e0s = (tid >> 5) * 8; // 16 strips of 8 edges
            float p0 = 0.f, p1 = 0.f;
            int cur = sSnk[e0s];
            #pragma unroll
            for (int j = 0; j < 8; j++) {
                float2 mv = *(const float2*)&sfMSG[(e0s + j) * 68 + 2 * c2];
                p0 += mv.x; p1 += mv.y;
                int nxt = (j < 7) ? sSnk[e0s + j + 1] : -1;
                if (nxt != cur) {
                    atomicAdd((__half2*)(inc + (size_t)cur * NM + 2 * c2),
                              __floats2half2_rn(p0, p1));
                    p0 = p1 = 0.f;
                    cur = nxt;
                }
            }
        }
    }
}

// =====================================================================
// Node kernel: 256 thr, full-tile cp.async pipeline; incoming is fp16 and
// lands DIRECTLY in the A tile (no convert pass). Zeroes incoming rows.
// smem (u32): NW1 [0,12288), NW2 [12288,20480), NB1 20480, NB2 20608,
//             NHS [20736,25088), NAB [25088,+2*6400) A bufs [64][100]
// =====================================================================
#define NW1 0
#define NW2 12288
#define NB1 20480
#define NB2 20608
#define NHS 20736
#define NAB 25088
#define NODE_SMEM_BYTES ((25088 + 2 * 6400) * 4)   // 151552

__device__ __forceinline__ void node_issue(uint32_t aBase, int buf, int b,
                                           int n0, int tid) {
    const char* stH = (const char*)(g_statesH + (size_t)b * NN * ND);
    const char* inc = (const char*)(g_incomingH + (size_t)b * NN * NM);
    uint32_t abuf = aBase + buf * 6400 * 4;
    // incoming fp16: 64 rows x 8 chunks -> A bytes [0,128) per row
    #pragma unroll
    for (int i = 0; i < 2; i++) {
        int idx = tid + i * 256;   // 0..511
        int row = idx >> 3, ch = idx & 7;
        int node = n0 + row;
        if (node < NN)
            CP_ASYNC16(abuf + (uint32_t)(row * 400 + ch * 16),
                       inc + (size_t)node * 128 + ch * 16);
    }
    // states fp16: 64 rows x 16 chunks -> A bytes [128,384) per row
    #pragma unroll
    for (int i = 0; i < 4; i++) {
        int idx = tid + i * 256;   // 0..1023
        int row = idx >> 4, ch = idx & 15;
        int node = n0 + row;
        if (node < NN)
            CP_ASYNC16(abuf + (uint32_t)(row * 400 + 128 + ch * 16),
                       stH + (size_t)node * 256 + ch * 16);
    }
}

__global__ __launch_bounds__(256, 1) void node_kernel(
    const float* __restrict__ w1, const float* __restrict__ b1,
    const float* __restrict__ w2, const float* __restrict__ b2)
{
    extern __shared__ uint32_t su[];
    float* sfB1 = (float*)(su + NB1);
    float* sfB2 = (float*)(su + NB2);

    const int tid = threadIdx.x;
    const int lid = tid & 31;
    const int wid = tid >> 5;
    const int wr = wid & 3;
    const int wc = wid >> 2;
    const uint32_t aBase = smem_u32(su + NAB);

    {
        int T0 = blockIdx.x;
        if (T0 < NT_NODE_TOT) {
            int b0 = T0 / NT_NODE_B;
            node_issue(aBase, 0, b0, (T0 - b0 * NT_NODE_B) * 64, tid);
        }
    }
    CP_COMMIT();

    for (int i = tid; i < 12 * 16 * 32; i += 256) {
        int s = i >> 9, f = (i >> 5) & 15, l = i & 31;
        int k = s * 16 + (l & 3) * 2, n = f * 8 + (l >> 2);
        uint2 v;
        v.x = pack_h2(w1[k * NH + n],       w1[(k + 1) * NH + n]);
        v.y = pack_h2(w1[(k + 8) * NH + n], w1[(k + 9) * NH + n]);
        *(uint2*)(su + NW1 + 2 * i) = v;
    }
    for (int i = tid; i < 8 * 16 * 32; i += 256) {
        int s = i >> 9, f = (i >> 5) & 15, l = i & 31;
        int k = s * 16 + (l & 3) * 2, n = f * 8 + (l >> 2);
        uint2 v;
        if (n < NU) {
            v.x = pack_h2(w2[k * NU + n],       w2[(k + 1) * NU + n]);
            v.y = pack_h2(w2[(k + 8) * NU + n], w2[(k + 9) * NU + n]);
        } else v.x = v.y = 0u;
        *(uint2*)(su + NW2 + 2 * i) = v;
    }
    if (tid < NH) sfB1[tid] = b1[tid];
    if (tid < 128) sfB2[tid] = (tid < NU) ? b2[tid] : 0.f;

    const int ar = wr * 16 + (lid >> 2);

    int it = 0;
    for (int T = blockIdx.x; T < NT_NODE_TOT; T += gridDim.x, it++) {
        const int b = T / NT_NODE_B;
        const int n0 = (T - b * NT_NODE_B) * 64;
        const int cb = it & 1;
        float* st = g_states + (size_t)b * NN * ND;
        __half* stH = g_statesH + (size_t)b * NN * ND;
        __half* incH = g_incomingH + (size_t)b * NN * NM;

        CP_WAIT0();
        __syncthreads();   // A tile cb ready (weights too on iter 0); NHS reuse safe

        // zero this tile's incoming rows (fp16, block-exclusive)
        {
            float4 z4 = make_float4(0.f, 0.f, 0.f, 0.f);
            #pragma unroll
            for (int t = 0; t < 2; t++) {
                int idx = tid + t * 256;   // 0..511
                int row = idx >> 3, q = idx & 7;
                int node = n0 + row;
                if (node < NN)
                    *(float4*)((char*)(incH + (size_t)node * NM) + q * 16) = z4;
            }
        }

        // issue next tile into other buffer
        {
            int Tn = T + gridDim.x;
            if (Tn < NT_NODE_TOT) {
                int bn = Tn / NT_NODE_B;
                node_issue(aBase, cb ^ 1, bn, (Tn - bn * NT_NODE_B) * 64, tid);
            }
        }
        CP_COMMIT();

        // GEMM1: [64 x 192] @ [192 x 128], 12 K-steps
        const uint32_t* A = su + NAB + cb * 6400;
        float acc[8][4];
        #pragma unroll
        for (int f = 0; f < 8; f++)
            #pragma unroll
            for (int j = 0; j < 4; j++) acc[f][j] = 0.f;

        #pragma unroll 4
        for (int sg = 0; sg < 12; sg++) {
            const int kw = sg * 8 + (lid & 3);
            uint32_t a0 = A[ar * 100 + kw];
            uint32_t a1 = A[(ar + 8) * 100 + kw];
            uint32_t a2 = A[ar * 100 + kw + 4];
            uint32_t a3 = A[(ar + 8) * 100 + kw + 4];
            #pragma unroll
            for (int f = 0; f < 8; f++) {
                uint2 bp = *(const uint2*)(su + NW1 +
                    ((sg * 16 + wc * 8 + f) * 32 + lid) * 2);
                mma_f16(acc[f], a0, a1, a2, a3, bp.x, bp.y);
            }
        }

        #pragma unroll
        for (int f = 0; f < 8; f++) {
            int nn0 = wc * 64 + f * 8 + 2 * (lid & 3);
            float bb0 = sfB1[nn0], bb1 = sfB1[nn0 + 1];
            int wcol = wc * 32 + f * 4 + (lid & 3);
            su[NHS + ar * 68 + wcol] =
                pack_h2(fmaxf(acc[f][0] + bb0, 0.f), fmaxf(acc[f][1] + bb1, 0.f));
            su[NHS + (ar + 8) * 68 + wcol] =
                pack_h2(fmaxf(acc[f][2] + bb0, 0.f), fmaxf(acc[f][3] + bb1, 0.f));
        }
        __syncthreads();

        float acc2[8][4];
        #pragma unroll
        for (int f = 0; f < 8; f++)
            #pragma unroll
            for (int j = 0; j < 4; j++) acc2[f][j] = 0.f;

        #pragma unroll 2
        for (int ks = 0; ks < 8; ks++) {
            const int kw = ks * 8 + (lid & 3);
            uint32_t a0 = su[NHS + ar * 68 + kw];
            uint32_t a1 = su[NHS + (ar + 8) * 68 + kw];
            uint32_t a2 = su[NHS + ar * 68 + kw + 4];
            uint32_t a3 = su[NHS + (ar + 8) * 68 + kw + 4];
            #pragma unroll
            for (int f = 0; f < 8; f++) {
                uint2 bp = *(const uint2*)(su + NW2 +
                    ((ks * 16 + wc * 8 + f) * 32 + lid) * 2);
                mma_f16(acc2[f], a0, a1, a2, a3, bp.x, bp.y);
            }
        }

        {
            const int node0 = n0 + ar, node1 = n0 + ar + 8;
            #pragma unroll
            for (int f = 0; f < 8; f++) {
                int cc = wc * 64 + f * 8 + 2 * (lid & 3);
                float bb0 = sfB2[cc], bb1 = sfB2[cc + 1];
                if (cc < NU) {
                    if (node0 < NN) {
                        float* d = st + (size_t)node0 * ND + 2;
                        float nv0 = d[cc] + acc2[f][0] + bb0;
                        float nv1 = d[cc + 1] + acc2[f][1] + bb1;
                        d[cc] = nv0; d[cc + 1] = nv1;
                        *(__half2*)(stH + (size_t)node0 * ND + 2 + cc) =
                            __floats2half2_rn(nv0, nv1);
                    }
                    if (node1 < NN) {
                        float* d = st + (size_t)node1 * ND + 2;
                        float nv0 = d[cc] + acc2[f][2] + bb0;
                        float nv1 = d[cc + 1] + acc2[f][3] + bb1;
                        d[cc] = nv0; d[cc + 1] = nv1;
                        *(__half2*)(stH + (size_t)node1 * ND + 2 + cc) =
                            __floats2half2_rn(nv0, nv1);
                    }
                }
            }
        }
    }
}

// =====================================================================
// Readout: fp16 mma m16n8k16 on statesH mirror, attn pre-scaled by 1024.
// =====================================================================
#define EXT_SAT 0
#define EXT_SS  1152
#define EXT_SMEM_U32 (1152 + 4352)   // 5504 u32 = 22016 B
#define NSPLIT 8
#define NCHUNK (NN / NSPLIT)   // 1250
#define ATT_SCALE 1024.0f
#define ATT_INV   0.0009765625f

__global__ __launch_bounds__(256) void extract_kernel(
    const float* __restrict__ attn, float* __restrict__ out)
{
    extern __shared__ uint32_t su[];
    const int tid = threadIdx.x;
    const int lid = tid & 31;
    const int wid = tid >> 5;
    const int wq = wid & 1;       // q half (16 rows)
    const int wd = wid >> 1;      // d quarter (32 cols)
    const int b = blockIdx.z, qt = blockIdx.y, ns = blockIdx.x;
    const int q0 = qt * 32;
    const int nbeg = ns * NCHUNK;
    const int nend = nbeg + NCHUNK;
    const __half* stH = g_statesH + (size_t)b * NN * ND;
    const float* at = attn + ((size_t)b * NQ + q0) * NN;
    const uint32_t ssBase = smem_u32(su + EXT_SS);

    float acc[4][4];
    #pragma unroll
    for (int f = 0; f < 4; f++)
        #pragma unroll
        for (int j = 0; j < 4; j++) acc[f][j] = 0.f;

    const int arow = wq * 16 + (lid >> 2);
    const int lm_km = (lid >> 3) & 1;
    const int lm_ng = lid >> 4;
    const int lm_r  = lid & 7;

    for (int n0 = nbeg; n0 < nend; n0 += 64) {
        __syncthreads();
        #pragma unroll
        for (int t = 0; t < 4; t++) {
            int idx = tid + t * 256;
            int q = idx >> 5, c = idx & 31;
            int n = n0 + 2 * c;
            float vx = 0.f, vy = 0.f;
            if (n + 1 < nend) {
                float2 v = *(const float2*)&at[(size_t)q * NN + n];
                vx = v.x; vy = v.y;
            } else if (n < nend) {
                vx = at[(size_t)q * NN + n];
            }
            su[EXT_SAT + q * 36 + c] = pack_h2(vx * ATT_SCALE, vy * ATT_SCALE);
        }
        #pragma unroll
        for (int t = 0; t < 16; t++) {
            int idx = tid + t * 256;
            int row = idx >> 6, c = idx & 63;
            int n = n0 + row;
            su[EXT_SS + row * 68 + c] =
                (n < nend) ? ((const uint32_t*)(stH + (size_t)n * ND))[c] : 0u;
        }
        __syncthreads();

        #pragma unroll
        for (int sg = 0; sg < 4; sg++) {
            const int kw = sg * 8 + (lid & 3);
            uint32_t a0 = su[EXT_SAT + arow * 36 + kw];
            uint32_t a1 = su[EXT_SAT + (arow + 8) * 36 + kw];
            uint32_t a2 = su[EXT_SAT + arow * 36 + kw + 4];
            uint32_t a3 = su[EXT_SAT + (arow + 8) * 36 + kw + 4];
            #pragma unroll
            for (int g = 0; g < 2; g++) {
                int nb = wd * 32 + g * 16;
                uint32_t addr = ssBase +
                    (uint32_t)((sg * 16 + lm_km * 8 + lm_r) * 272 +
                               (nb + lm_ng * 8) * 2);
                uint32_t r0, r1, r2, r3;
                asm volatile(
                    "ldmatrix.sync.aligned.m8n8.x4.trans.shared.b16 "
                    "{%0,%1,%2,%3}, [%4];"
                    : "=r"(r0), "=r"(r1), "=r"(r2), "=r"(r3) : "r"(addr));
                mma_f16(acc[2 * g],     a0, a1, a2, a3, r0, r1);
                mma_f16(acc[2 * g + 1], a0, a1, a2, a3, r2, r3);
            }
        }
    }

    #pragma unroll
    for (int f = 0; f < 4; f++) {
        int d = wd * 32 + f * 8 + (lid & 3) * 2;
        int q = q0 + wq * 16 + (lid >> 2);
        float* drow = out + ((size_t)(b * NQ + q)) * OUTC + NP + d;
        atomicAdd(drow,     acc[f][0] * ATT_INV);
        atomicAdd(drow + 1, acc[f][1] * ATT_INV);
        float* drow2 = out + ((size_t)(b * NQ + q + 8)) * OUTC + NP + d;
        atomicAdd(drow2,     acc[f][2] * ATT_INV);
        atomicAdd(drow2 + 1, acc[f][3] * ATT_INV);
    }
}

// =====================================================================
extern "C" void kernel_launch(void* const* d_in, const int* in_sizes, int n_in,
                              void* d_out, int out_size)
{
    const float* nodes = (const float*)d_in[0];
    const float* poses = (const float*)d_in[1];
    const float* attn  = (const float*)d_in[2];
    const int*   esrc  = (const int*)d_in[3];
    const int*   esnk  = (const int*)d_in[4];
    const float* w1e   = (const float*)d_in[5];
    const float* b1e   = (const float*)d_in[6];
    const float* w2e   = (const float*)d_in[7];
    const float* b2e   = (const float*)d_in[8];
    const float* w1n   = (const float*)d_in[9];
    const float* b1n   = (const float*)d_in[10];
    const float* w2n   = (const float*)d_in[11];
    const float* b2n   = (const float*)d_in[12];
    float* out = (float*)d_out;

    cudaFuncSetAttribute(proj_kernel, cudaFuncAttributeMaxDynamicSharedMemorySize,
                         PROJ_SMEM_BYTES);
    cudaFuncSetAttribute(edge_kernel, cudaFuncAttributeMaxDynamicSharedMemorySize,
                         EDGE_SMEM_BYTES);
    cudaFuncSetAttribute(node_kernel, cudaFuncAttributeMaxDynamicSharedMemorySize,
                         NODE_SMEM_BYTES);

    // copy + fp16 mirror + csr count zero + out init (fused)
    copy_states_kernel<<<(NB * NN * ND / 4 + 255) / 256, 256>>>(nodes, poses, out);

    // CSR chain (hist also zeroes fp16 incoming)
    csr_hist_kernel<<<(NE + 255) / 256, 256>>>(esnk);
    csr_scan_kernel<<<1, 1024>>>();
    csr_scatter_kernel<<<(NE + 255) / 256, 256>>>(esrc, esnk);
    tile_meta_kernel<<<NTE_B, TEE>>>();

    for (int s = 0; s < 3; s++) {
        proj_kernel<<<148, 256, PROJ_SMEM_BYTES>>>(w1e);
        edge_kernel<<<148, 512, EDGE_SMEM_BYTES>>>(b1e, w2e, b2e);
        node_kernel<<<148, 256, NODE_SMEM_BYTES>>>(w1n, b1n, w2n, b2n);
    }
    extract_kernel<<<dim3(NSPLIT, NQ / 32, NB), 256, EXT_SMEM_U32 * 4>>>(attn, out);
}

// round 17
// speedup vs baseline: 1.1325x; 1.0140x over previous
#include <cuda_runtime.h>
#include <cuda_fp16.h>
#include <cstdint>

#define NB 4
#define NN 10000
#define NE 160000
#define NQ 256
#define ND 128
#define NM 64
#define NU 126
#define NH 128
#define NP 7
#define OUTC (NP + ND)   // 135

#define TEE 128                    // edges per edge-tile
#define NTE_B (NE / TEE)           // 1250
#define NTE_TOT (NTE_B * NB)       // 5000

#define NT_NODE_B 157              // ceil(10000/64)
#define NT_NODE_TOT (NT_NODE_B * NB)

#define NPT_B 79                   // ceil(10000/128) proj tiles per batch
#define NPT_TOT (NPT_B * NB)       // 316

// -------- scratch (static device globals: allocation-free) --------
__device__ float g_states[NB * NN * ND];                  // 20.5 MB
__device__ __align__(16) __half g_statesH[NB * NN * ND];  // 10.2 MB fp16 mirror
__device__ __align__(16) __half g_incomingH[NB * NN * NM];// 5.1 MB fp16 accumulator
__device__ __align__(16) __half g_P1[NB * NN * NH];       // src projections
__device__ __align__(16) __half g_P2[NB * NN * NH];       // snk projections
// CSR + tile metadata
__device__ int g_count[NN];
__device__ int g_cur[NN];
__device__ int g_sortedSrc[NE];
__device__ int g_sortedSnk[NE];
__device__ int g_li[NE];               // per-edge local unique-sink index
__device__ int g_uniq[NTE_B * TEE];    // per-tile unique sink list
__device__ int g_ucnt[NTE_B];          // per-tile unique count

// ============================ helpers ============================
__device__ __forceinline__ uint32_t smem_u32(const void* p) {
    uint32_t a;
    asm("{ .reg .u64 t; cvta.to.shared.u64 t, %1; cvt.u32.u64 %0, t; }"
        : "=r"(a) : "l"(p));
    return a;
}
__device__ __forceinline__ uint32_t pack_h2(float a, float b) {
    __half2 h = __floats2half2_rn(a, b);
    return *reinterpret_cast<uint32_t*>(&h);
}
__device__ __forceinline__ void mma_f16(float* c, uint32_t a0, uint32_t a1,
                                        uint32_t a2, uint32_t a3,
                                        uint32_t b0, uint32_t b1) {
    asm volatile(
        "mma.sync.aligned.m16n8k16.row.col.f32.f16.f16.f32 "
        "{%0,%1,%2,%3}, {%4,%5,%6,%7}, {%8,%9}, {%0,%1,%2,%3};"
        : "+f"(c[0]), "+f"(c[1]), "+f"(c[2]), "+f"(c[3])
        : "r"(a0), "r"(a1), "r"(a2), "r"(a3), "r"(b0), "r"(b1));
}
#define CP_ASYNC16(dst, src) \
    asm volatile("cp.async.cg.shared.global [%0], [%1], 16;" \
                 :: "r"(dst), "l"(src) : "memory")
#define CP_COMMIT() asm volatile("cp.async.commit_group;" ::: "memory")
#define CP_WAIT0()  asm volatile("cp.async.wait_group 0;" ::: "memory")

// -------- utility kernels --------
// copy + fp16 mirror + csr count zero + out-pose init (independent ranges)
__global__ void copy_states_kernel(const float* __restrict__ src,
                                   const float* __restrict__ poses,
                                   float* __restrict__ out) {
    int i = blockIdx.x * blockDim.x + threadIdx.x;
    const int n = NB * NN * ND / 4;
    if (i < n) {
        float4 v = reinterpret_cast<const float4*>(src)[i];
        reinterpret_cast<float4*>(g_states)[i] = v;
        __half2* mh = reinterpret_cast<__half2*>(g_statesH);
        mh[2 * i]     = __floats2half2_rn(v.x, v.y);
        mh[2 * i + 1] = __floats2half2_rn(v.z, v.w);
    }
    if (i < NN) g_count[i] = 0;
    if (i < NB * NQ * OUTC) {
        int r = i / OUTC, c = i - r * OUTC;
        out[i] = (c < NP) ? poses[r * NP + c] : 0.f;
    }
}

// -------- CSR build (once per launch; graph static) --------
__global__ void csr_hist_kernel(const int* __restrict__ esnk) {
    int i = blockIdx.x * blockDim.x + threadIdx.x;
    float4 z = make_float4(0.f, 0.f, 0.f, 0.f);
    #pragma unroll
    for (int t = 0; t < 2; t++) {
        int j = i + t * 160000;
        if (j < NB * NN * NM * 2 / 16)
            reinterpret_cast<float4*>(g_incomingH)[j] = z;
    }
    if (i < NE) atomicAdd(&g_count[esnk[i]], 1);
}
__global__ void csr_scan_kernel() {
    __shared__ int part[1024];
    int t = threadIdx.x;
    int beg = t * 10;
    int end = beg + 10 < NN ? beg + 10 : NN;
    int s = 0;
    for (int i = beg; i < end; i++) s += g_count[i];
    part[t] = s;
    __syncthreads();
    for (int d = 1; d < 1024; d <<= 1) {
        int v = (t >= d) ? part[t - d] : 0;
        __syncthreads();
        part[t] += v;
        __syncthreads();
    }
    int base = (t > 0) ? part[t - 1] : 0;
    for (int i = beg; i < end; i++) {
        g_cur[i] = base;
        base += g_count[i];
    }
}
__global__ void csr_scatter_kernel(const int* __restrict__ esrc,
                                   const int* __restrict__ esnk) {
    int i = blockIdx.x * blockDim.x + threadIdx.x;
    if (i < NE) {
        int s = esnk[i];
        int p = atomicAdd(&g_cur[s], 1);
        g_sortedSrc[p] = esrc[i];
        g_sortedSnk[p] = s;
    }
}
__global__ void tile_meta_kernel() {
    __shared__ int fl[TEE];
    int t = blockIdx.x, tid = threadIdx.x;
    int e = t * TEE + tid;
    int s = g_sortedSnk[e];
    int flag = (tid == 0) || (s != g_sortedSnk[e - 1]);
    fl[tid] = flag;
    __syncthreads();
    for (int d = 1; d < TEE; d <<= 1) {
        int v = (tid >= d) ? fl[tid - d] : 0;
        __syncthreads();
        fl[tid] += v;
        __syncthreads();
    }
    int li = fl[tid] - 1;
    g_li[e] = li;
    if (flag) g_uniq[t * TEE + li] = s;
    if (tid == TEE - 1) g_ucnt[t] = fl[tid];
}

// =====================================================================
// Standalone projection kernel (step 0 only): P = statesH @ [W1top|W1bot]
// =====================================================================
#define PW 0
#define PA 16384
#define PROJ_SMEM_BYTES ((16384 + 2 * 8704) * 4)   // 135168

__device__ __forceinline__ void proj_issue(uint32_t aBase, int b, int n0, int tid) {
    const __half* stH = g_statesH + (size_t)b * NN * ND;
    #pragma unroll
    for (int t = 0; t < 8; t++) {
        int idx = tid + t * 256;       // 0..2047
        int row = idx >> 4, ch = idx & 15;
        int node = n0 + row;
        if (node >= NN) node = NN - 1;   // clamp; stores are guarded
        uint32_t dst = aBase + row * 272 + ch * 16;
        CP_ASYNC16(dst, stH + (size_t)node * ND + ch * 8);
    }
}

__global__ __launch_bounds__(256, 1) void proj_kernel(
    const float* __restrict__ w1)
{
    extern __shared__ uint32_t su[];
    const int tid = threadIdx.x;
    const int lid = tid & 31;
    const int wid = tid >> 5;
    const int wm = wid >> 1;     // 4 row groups of 32 nodes
    const int wn = wid & 1;      // 2 col halves of 128 h'
    const uint32_t aBase0 = smem_u32(su + PA);

    {
        int T0 = blockIdx.x;
        if (T0 < NPT_TOT) {
            int b0 = T0 / NPT_B;
            proj_issue(aBase0, b0, (T0 - b0 * NPT_B) * 128, tid);
        }
    }
    CP_COMMIT();

    for (int i = tid; i < 8 * 32 * 32; i += 256) {
        int s = i >> 10;
        int f = (i >> 5) & 31;
        int l = i & 31;
        int colg = f * 8 + (l >> 2);
        int krow = s * 16 + (l & 3) * 2;
        int koff = (colg >= 128) ? 128 : 0;
        int col = colg & 127;
        uint2 v;
        v.x = pack_h2(w1[(koff + krow) * NH + col],     w1[(koff + krow + 1) * NH + col]);
        v.y = pack_h2(w1[(koff + krow + 8) * NH + col], w1[(koff + krow + 9) * NH + col]);
        *(uint2*)(su + PW + 2 * i) = v;
    }

    int it = 0;
    for (int T = blockIdx.x; T < NPT_TOT; T += gridDim.x, it++) {
        const int b = T / NPT_B;
        const int n0 = (T - b * NPT_B) * 128;

        CP_WAIT0();
        __syncthreads();

        {
            int Tn = T + gridDim.x;
            if (Tn < NPT_TOT) {
                int bn = Tn / NPT_B;
                proj_issue(aBase0 + ((it + 1) & 1) * 8704 * 4,
                           bn, (Tn - bn * NPT_B) * 128, tid);
            }
        }
        CP_COMMIT();

        const uint32_t* A = su + PA + (it & 1) * 8704;
        #pragma unroll 1
        for (int mf = 0; mf < 2; mf++) {
            float acc[16][4];
            #pragma unroll
            for (int f = 0; f < 16; f++)
                #pragma unroll
                for (int j = 0; j < 4; j++) acc[f][j] = 0.f;

            const int r0 = wm * 32 + mf * 16 + (lid >> 2);
            #pragma unroll
            for (int sg = 0; sg < 8; sg++) {
                const int kw = sg * 8 + (lid & 3);
                uint32_t a0 = A[r0 * 68 + kw];
                uint32_t a1 = A[(r0 + 8) * 68 + kw];
                uint32_t a2 = A[r0 * 68 + kw + 4];
                uint32_t a3 = A[(r0 + 8) * 68 + kw + 4];
                #pragma unroll
                for (int f = 0; f < 16; f++) {
                    uint2 bp = *(const uint2*)(su + PW +
                        ((sg * 32 + wn * 16 + f) * 32 + lid) * 2);
                    mma_f16(acc[f], a0, a1, a2, a3, bp.x, bp.y);
                }
            }
            #pragma unroll
            for (int f = 0; f < 16; f++) {
                const float* c = acc[f];
                int colg = wn * 128 + f * 8 + (lid & 3) * 2;
                __half* P = (colg < 128) ? g_P1 : g_P2;
                int col = colg & 127;
                int node0 = n0 + r0, node1 = n0 + r0 + 8;
                if (node0 < NN)
                    *(uint32_t*)(P + ((size_t)b * NN + node0) * NH + col) =
                        pack_h2(c[0], c[1]);
                if (node1 < NN)
                    *(uint32_t*)(P + ((size_t)b * NN + node1) * NH + col) =
                        pack_h2(c[2], c[3]);
            }
        }
        __syncthreads();
    }
}

// =====================================================================
// Edge kernel (unchanged champion): gather P1[src] + P2[unique], H in
// registers, GEMM2, segmented scatter with f16x2 atomics. 512 thr.
// =====================================================================
#define EW2O  0
#define EB2O  4096
#define SLIO  4160
#define SSKO  4416
#define EMSO  4672
#define GP1O  13376
#define GP2O  30784
#define EDGE_SMEM_BYTES (48192 * 4)   // 192768

__device__ __forceinline__ void edge_issue(
    uint32_t gp1Base, uint32_t gp2Base, uint32_t liBase, uint32_t skBase,
    int buf, int t, int b, int tid)
{
    const int eb = t * TEE;
    const char* P1 = (const char*)(g_P1 + (size_t)b * NN * NH);
    const char* P2 = (const char*)(g_P2 + (size_t)b * NN * NH);
    uint32_t g1 = gp1Base + buf * 8704 * 4;
    uint32_t g2 = gp2Base + buf * 8704 * 4;
    #pragma unroll
    for (int i = 0; i < 4; i++) {
        int idx = tid + i * 512;        // 0..2047
        int row = idx >> 4, ch = idx & 15;
        int node = g_sortedSrc[eb + row];
        CP_ASYNC16(g1 + (uint32_t)(row * 272 + ch * 16),
                   P1 + (size_t)node * 256 + ch * 16);
    }
    int uc = g_ucnt[t] * 16;
    for (int i = tid; i < uc; i += 512) {
        int row = i >> 4, ch = i & 15;
        int node = g_uniq[t * TEE + row];
        CP_ASYNC16(g2 + (uint32_t)(row * 272 + ch * 16),
                   P2 + (size_t)node * 256 + ch * 16);
    }
    if (tid < 32)
        CP_ASYNC16(liBase + buf * 512 + tid * 16,
                   (const char*)(g_li + eb) + tid * 16);
    else if (tid < 64)
        CP_ASYNC16(skBase + buf * 512 + (tid - 32) * 16,
                   (const char*)(g_sortedSnk + eb) + (tid - 32) * 16);
}

__global__ __launch_bounds__(512, 1) void edge_kernel(
    const float* __restrict__ b1,
    const float* __restrict__ w2, const float* __restrict__ b2)
{
    extern __shared__ uint32_t su[];
    float* sfB2 = (float*)(su + EB2O);
    int* sLiB = (int*)(su + SLIO);
    int* sSnkB = (int*)(su + SSKO);
    float* sfMSG = (float*)(su + EMSO);

    const int tid = threadIdx.x;
    const int lid = tid & 31;
    const int wid = tid >> 5;          // 0..15
    const int wg  = wid >> 1;          // 8 row groups of 16 edges
    const int wc  = wid & 1;           // column half of NM
    const uint32_t gp1Base = smem_u32(su + GP1O);
    const uint32_t gp2Base = smem_u32(su + GP2O);
    const uint32_t liBase  = smem_u32(su + SLIO);
    const uint32_t skBase  = smem_u32(su + SSKO);

    {
        int T0 = blockIdx.x;
        int b0 = T0 / NTE_B;
        edge_issue(gp1Base, gp2Base, liBase, skBase, 0, T0 - b0 * NTE_B, b0, tid);
    }
    CP_COMMIT();

    for (int i = tid; i < 8 * 8 * 32; i += 512) {
        int s = i >> 8, f = (i >> 5) & 7, l = i & 31;
        int k = s * 16 + (l & 3) * 2, n = f * 8 + (l >> 2);
        uint2 v;
        v.x = pack_h2(w2[k * NM + n],       w2[(k + 1) * NM + n]);
        v.y = pack_h2(w2[(k + 8) * NM + n], w2[(k + 9) * NM + n]);
        *(uint2*)(su + EW2O + 2 * i) = v;
    }
    if (tid < NM) sfB2[tid] = b2[tid];

    __half2 b1r[16];
    #pragma unroll
    for (int t = 0; t < 16; t++) {
        int c = 4 * t + (lid & 3);
        b1r[t] = __floats2half2_rn(b1[2 * c], b1[2 * c + 1]);
    }

    const int arq = wg * 16 + (lid >> 2);
    const __half2 hz = __floats2half2_rn(0.f, 0.f);

    int it = 0;
    for (int T = blockIdx.x; T < NTE_TOT; T += gridDim.x, it++) {
        const int b = T / NTE_B;
        const int cb = it & 1;
        __half* inc = g_incomingH + (size_t)b * NN * NM;

        CP_WAIT0();
        __syncthreads();

        const uint32_t* G1 = su + GP1O + cb * 8704;
        const uint32_t* G2 = su + GP2O + cb * 8704;
        const int* sLi = sLiB + cb * TEE;
        const int li0 = sLi[arq], li1 = sLi[arq + 8];
        uint32_t hA[8][4];
        #pragma unroll
        for (int sg = 0; sg < 8; sg++) {
            const int c0 = sg * 8 + (lid & 3);
            const int c1 = c0 + 4;
            __half2 v;
            v = __hmax2(__hadd2(__hadd2(*(const __half2*)&G1[arq * 68 + c0],
                                        *(const __half2*)&G2[li0 * 68 + c0]),
                                b1r[2 * sg]), hz);
            hA[sg][0] = *(uint32_t*)&v;
            v = __hmax2(__hadd2(__hadd2(*(const __half2*)&G1[(arq + 8) * 68 + c0],
                                        *(const __half2*)&G2[li1 * 68 + c0]),
                                b1r[2 * sg]), hz);
            hA[sg][1] = *(uint32_t*)&v;
            v = __hmax2(__hadd2(__hadd2(*(const __half2*)&G1[arq * 68 + c1],
                                        *(const __half2*)&G2[li0 * 68 + c1]),
                                b1r[2 * sg + 1]), hz);
            hA[sg][2] = *(uint32_t*)&v;
            v = __hmax2(__hadd2(__hadd2(*(const __half2*)&G1[(arq + 8) * 68 + c1],
                                        *(const __half2*)&G2[li1 * 68 + c1]),
                                b1r[2 * sg + 1]), hz);
            hA[sg][3] = *(uint32_t*)&v;
        }

        {
            int Tn = T + gridDim.x;
            if (Tn < NTE_TOT) {
                int bn = Tn / NTE_B;
                edge_issue(gp1Base, gp2Base, liBase, skBase,
                           cb ^ 1, Tn - bn * NTE_B, bn, tid);
            }
        }
        CP_COMMIT();

        float acc2[4][4];
        #pragma unroll
        for (int f = 0; f < 4; f++)
            #pragma unroll
            for (int j = 0; j < 4; j++) acc2[f][j] = 0.f;

        #pragma unroll
        for (int sg = 0; sg < 8; sg++) {
            #pragma unroll
            for (int f = 0; f < 4; f++) {
                uint2 bp = *(const uint2*)(su + EW2O +
                    ((sg * 8 + wc * 4 + f) * 32 + lid) * 2);
                mma_f16(acc2[f], hA[sg][0], hA[sg][1], hA[sg][2], hA[sg][3],
                        bp.x, bp.y);
            }
        }

        #pragma unroll
        for (int f = 0; f < 4; f++) {
            int m = wc * 32 + f * 8 + 2 * (lid & 3);
            float bb0 = sfB2[m], bb1 = sfB2[m + 1];
            sfMSG[arq * 68 + m]           = acc2[f][0] + bb0;
            sfMSG[arq * 68 + m + 1]       = acc2[f][1] + bb1;
            sfMSG[(arq + 8) * 68 + m]     = acc2[f][2] + bb0;
            sfMSG[(arq + 8) * 68 + m + 1] = acc2[f][3] + bb1;
        }
        __syncthreads();

        {
            const int* sSnk = sSnkB + cb * TEE;
            const int c2 = tid & 31;
            const int e0s = (tid >> 5) * 8;
            float p0 = 0.f, p1 = 0.f;
            int cur = sSnk[e0s];
            #pragma unroll
            for (int j = 0; j < 8; j++) {
                float2 mv = *(const float2*)&sfMSG[(e0s + j) * 68 + 2 * c2];
                p0 += mv.x; p1 += mv.y;
                int nxt = (j < 7) ? sSnk[e0s + j + 1] : -1;
                if (nxt != cur) {
                    atomicAdd((__half2*)(inc + (size_t)cur * NM + 2 * c2),
                              __floats2half2_rn(p0, p1));
                    p0 = p1 = 0.f;
                    cur = nxt;
                }
            }
        }
    }
}

// =====================================================================
// Node kernel (256 thr) + FUSED projection of updated states:
// after the state-update epilogue, new fp16 states are written back into
// the smem A tile, then P1/P2 = newstates @ [W1e_top|W1e_bot] from smem.
// smem (u32): NW1 [0,12288), NW2 [12288,20480), NB1 20480, NB2 20608,
//   NHS [20736,25088), NAB [25088,+2*6400)=..37888, PWE [37888,54272)
// =====================================================================
#define NW1 0
#define NW2 12288
#define NB1 20480
#define NB2 20608
#define NHS 20736
#define NAB 25088
#define PWE 37888
#define NODE_SMEM_BYTES (54272 * 4)   // 217088

__device__ __forceinline__ void node_issue(uint32_t aBase, int buf, int b,
                                           int n0, int tid) {
    const char* stH = (const char*)(g_statesH + (size_t)b * NN * ND);
    const char* inc = (const char*)(g_incomingH + (size_t)b * NN * NM);
    uint32_t abuf = aBase + buf * 6400 * 4;
    #pragma unroll
    for (int i = 0; i < 2; i++) {
        int idx = tid + i * 256;   // 0..511
        int row = idx >> 3, ch = idx & 7;
        int node = n0 + row;
        if (node < NN)
            CP_ASYNC16(abuf + (uint32_t)(row * 400 + ch * 16),
                       inc + (size_t)node * 128 + ch * 16);
    }
    #pragma unroll
    for (int i = 0; i < 4; i++) {
        int idx = tid + i * 256;   // 0..1023
        int row = idx >> 4, ch = idx & 15;
        int node = n0 + row;
        if (node < NN)
            CP_ASYNC16(abuf + (uint32_t)(row * 400 + 128 + ch * 16),
                       stH + (size_t)node * 256 + ch * 16);
    }
}

__global__ __launch_bounds__(256, 1) void node_kernel(
    const float* __restrict__ w1, const float* __restrict__ b1,
    const float* __restrict__ w2, const float* __restrict__ b2,
    const float* __restrict__ w1e, int do_proj)
{
    extern __shared__ uint32_t su[];
    float* sfB1 = (float*)(su + NB1);
    float* sfB2 = (float*)(su + NB2);

    const int tid = threadIdx.x;
    const int lid = tid & 31;
    const int wid = tid >> 5;
    const int wr = wid & 3;
    const int wc = wid >> 2;
    const uint32_t aBase = smem_u32(su + NAB);

    {
        int T0 = blockIdx.x;
        if (T0 < NT_NODE_TOT) {
            int b0 = T0 / NT_NODE_B;
            node_issue(aBase, 0, b0, (T0 - b0 * NT_NODE_B) * 64, tid);
        }
    }
    CP_COMMIT();

    for (int i = tid; i < 12 * 16 * 32; i += 256) {
        int s = i >> 9, f = (i >> 5) & 15, l = i & 31;
        int k = s * 16 + (l & 3) * 2, n = f * 8 + (l >> 2);
        uint2 v;
        v.x = pack_h2(w1[k * NH + n],       w1[(k + 1) * NH + n]);
        v.y = pack_h2(w1[(k + 8) * NH + n], w1[(k + 9) * NH + n]);
        *(uint2*)(su + NW1 + 2 * i) = v;
    }
    for (int i = tid; i < 8 * 16 * 32; i += 256) {
        int s = i >> 9, f = (i >> 5) & 15, l = i & 31;
        int k = s * 16 + (l & 3) * 2, n = f * 8 + (l >> 2);
        uint2 v;
        if (n < NU) {
            v.x = pack_h2(w2[k * NU + n],       w2[(k + 1) * NU + n]);
            v.y = pack_h2(w2[(k + 8) * NU + n], w2[(k + 9) * NU + n]);
        } else v.x = v.y = 0u;
        *(uint2*)(su + NW2 + 2 * i) = v;
    }
    if (do_proj) {
        // W1e fragments for the fused projection: [8 sg][32 nf][32][2]
        for (int i = tid; i < 8 * 32 * 32; i += 256) {
            int s = i >> 10;
            int f = (i >> 5) & 31;
            int l = i & 31;
            int colg = f * 8 + (l >> 2);
            int krow = s * 16 + (l & 3) * 2;
            int koff = (colg >= 128) ? 128 : 0;
            int col = colg & 127;
            uint2 v;
            v.x = pack_h2(w1e[(koff + krow) * NH + col],
                          w1e[(koff + krow + 1) * NH + col]);
            v.y = pack_h2(w1e[(koff + krow + 8) * NH + col],
                          w1e[(koff + krow + 9) * NH + col]);
            *(uint2*)(su + PWE + 2 * i) = v;
        }
    }
    if (tid < NH) sfB1[tid] = b1[tid];
    if (tid < 128) sfB2[tid] = (tid < NU) ? b2[tid] : 0.f;

    const int ar = wr * 16 + (lid >> 2);

    int it = 0;
    for (int T = blockIdx.x; T < NT_NODE_TOT; T += gridDim.x, it++) {
        const int b = T / NT_NODE_B;
        const int n0 = (T - b * NT_NODE_B) * 64;
        const int cb = it & 1;
        float* st = g_states + (size_t)b * NN * ND;
        __half* stH = g_statesH + (size_t)b * NN * ND;
        __half* incH = g_incomingH + (size_t)b * NN * NM;

        CP_WAIT0();
        __syncthreads();   // A tile cb ready; NHS/A reuse safe

        // zero this tile's incoming rows (fp16, block-exclusive)
        {
            float4 z4 = make_float4(0.f, 0.f, 0.f, 0.f);
            #pragma unroll
            for (int t = 0; t < 2; t++) {
                int idx = tid + t * 256;   // 0..511
                int row = idx >> 3, q = idx & 7;
                int node = n0 + row;
                if (node < NN)
                    *(float4*)((char*)(incH + (size_t)node * NM) + q * 16) = z4;
            }
        }

        // issue next tile into other buffer
        {
            int Tn = T + gridDim.x;
            if (Tn < NT_NODE_TOT) {
                int bn = Tn / NT_NODE_B;
                node_issue(aBase, cb ^ 1, bn, (Tn - bn * NT_NODE_B) * 64, tid);
            }
        }
        CP_COMMIT();

        // GEMM1: [64 x 192] @ [192 x 128], 12 K-steps
        uint32_t* A = su + NAB + cb * 6400;
        float acc[8][4];
        #pragma unroll
        for (int f = 0; f < 8; f++)
            #pragma unroll
            for (int j = 0; j < 4; j++) acc[f][j] = 0.f;

        #pragma unroll 4
        for (int sg = 0; sg < 12; sg++) {
            const int kw = sg * 8 + (lid & 3);
            uint32_t a0 = A[ar * 100 + kw];
            uint32_t a1 = A[(ar + 8) * 100 + kw];
            uint32_t a2 = A[ar * 100 + kw + 4];
            uint32_t a3 = A[(ar + 8) * 100 + kw + 4];
            #pragma unroll
            for (int f = 0; f < 8; f++) {
                uint2 bp = *(const uint2*)(su + NW1 +
                    ((sg * 16 + wc * 8 + f) * 32 + lid) * 2);
                mma_f16(acc[f], a0, a1, a2, a3, bp.x, bp.y);
            }
        }

        #pragma unroll
        for (int f = 0; f < 8; f++) {
            int nn0 = wc * 64 + f * 8 + 2 * (lid & 3);
            float bb0 = sfB1[nn0], bb1 = sfB1[nn0 + 1];
            int wcol = wc * 32 + f * 4 + (lid & 3);
            su[NHS + ar * 68 + wcol] =
                pack_h2(fmaxf(acc[f][0] + bb0, 0.f), fmaxf(acc[f][1] + bb1, 0.f));
            su[NHS + (ar + 8) * 68 + wcol] =
                pack_h2(fmaxf(acc[f][2] + bb0, 0.f), fmaxf(acc[f][3] + bb1, 0.f));
        }
        __syncthreads();

        float acc2[8][4];
        #pragma unroll
        for (int f = 0; f < 8; f++)
            #pragma unroll
            for (int j = 0; j < 4; j++) acc2[f][j] = 0.f;

        #pragma unroll 2
        for (int ks = 0; ks < 8; ks++) {
            const int kw = ks * 8 + (lid & 3);
            uint32_t a0 = su[NHS + ar * 68 + kw];
            uint32_t a1 = su[NHS + (ar + 8) * 68 + kw];
            uint32_t a2 = su[NHS + ar * 68 + kw + 4];
            uint32_t a3 = su[NHS + (ar + 8) * 68 + kw + 4];
            #pragma unroll
            for (int f = 0; f < 8; f++) {
                uint2 bp = *(const uint2*)(su + NW2 +
                    ((ks * 16 + wc * 8 + f) * 32 + lid) * 2);
                mma_f16(acc2[f], a0, a1, a2, a3, bp.x, bp.y);
            }
        }

        // state update: global fp32 + fp16 mirror + (if do_proj) smem A tile
        {
            const int node0 = n0 + ar, node1 = n0 + ar + 8;
            #pragma unroll
            for (int f = 0; f < 8; f++) {
                int cc = wc * 64 + f * 8 + 2 * (lid & 3);
                float bb0 = sfB2[cc], bb1 = sfB2[cc + 1];
                if (cc < NU) {
                    if (node0 < NN) {
                        float* d = st + (size_t)node0 * ND + 2;
                        float nv0 = d[cc] + acc2[f][0] + bb0;
                        float nv1 = d[cc + 1] + acc2[f][1] + bb1;
                        d[cc] = nv0; d[cc + 1] = nv1;
                        uint32_t h = pack_h2(nv0, nv1);
                        *(uint32_t*)(stH + (size_t)node0 * ND + 2 + cc) = h;
                        if (do_proj) A[ar * 100 + 33 + cc / 2] = h;
                    }
                    if (node1 < NN) {
                        float* d = st + (size_t)node1 * ND + 2;
                        float nv0 = d[cc] + acc2[f][2] + bb0;
                        float nv1 = d[cc + 1] + acc2[f][3] + bb1;
                        d[cc] = nv0; d[cc + 1] = nv1;
                        uint32_t h = pack_h2(nv0, nv1);
                        *(uint32_t*)(stH + (size_t)node1 * ND + 2 + cc) = h;
                        if (do_proj) A[(ar + 8) * 100 + 33 + cc / 2] = h;
                    }
                }
            }
        }

        // ---- fused projection: P = newstates(smem A) @ [W1e_top|W1e_bot]
        if (do_proj) {
            __syncthreads();   // all warps' A-state updates visible
            #pragma unroll 1
            for (int mf = 0; mf < 2; mf++) {
                float pacc[8][4];
                #pragma unroll
                for (int f = 0; f < 8; f++)
                    #pragma unroll
                    for (int j = 0; j < 4; j++) pacc[f][j] = 0.f;

                #pragma unroll
                for (int sg = 0; sg < 8; sg++) {
                    const int kw = 32 + sg * 8 + (lid & 3);
                    uint32_t a0 = A[ar * 100 + kw];
                    uint32_t a1 = A[(ar + 8) * 100 + kw];
                    uint32_t a2 = A[ar * 100 + kw + 4];
                    uint32_t a3 = A[(ar + 8) * 100 + kw + 4];
                    #pragma unroll
                    for (int f = 0; f < 8; f++) {
                        uint2 bp = *(const uint2*)(su + PWE +
                            ((sg * 32 + wc * 16 + mf * 8 + f) * 32 + lid) * 2);
                        mma_f16(pacc[f], a0, a1, a2, a3, bp.x, bp.y);
                    }
                }
                #pragma unroll
                for (int f = 0; f < 8; f++) {
                    const float* c = pacc[f];
                    int colg = wc * 128 + mf * 64 + f * 8 + (lid & 3) * 2;
                    __half* P = (colg < 128) ? g_P1 : g_P2;
                    int col = colg & 127;
                    int node0 = n0 + ar, node1 = n0 + ar + 8;
                    if (node0 < NN)
                        *(uint32_t*)(P + ((size_t)b * NN + node0) * NH + col) =
                            pack_h2(c[0], c[1]);
                    if (node1 < NN)
                        *(uint32_t*)(P + ((size_t)b * NN + node1) * NH + col) =
                            pack_h2(c[2], c[3]);
                }
            }
        }
        // next iteration's top barrier guards NHS/A reuse
    }
}

// =====================================================================
// Readout: fp16 mma m16n8k16 on statesH mirror, attn pre-scaled by 1024.
// =====================================================================
#define EXT_SAT 0
#define EXT_SS  1152
#define EXT_SMEM_U32 (1152 + 4352)   // 5504 u32 = 22016 B
#define NSPLIT 8
#define NCHUNK (NN / NSPLIT)   // 1250
#define ATT_SCALE 1024.0f
#define ATT_INV   0.0009765625f

__global__ __launch_bounds__(256) void extract_kernel(
    const float* __restrict__ attn, float* __restrict__ out)
{
    extern __shared__ uint32_t su[];
    const int tid = threadIdx.x;
    const int lid = tid & 31;
    const int wid = tid >> 5;
    const int wq = wid & 1;
    const int wd = wid >> 1;
    const int b = blockIdx.z, qt = blockIdx.y, ns = blockIdx.x;
    const int q0 = qt * 32;
    const int nbeg = ns * NCHUNK;
    const int nend = nbeg + NCHUNK;
    const __half* stH = g_statesH + (size_t)b * NN * ND;
    const float* at = attn + ((size_t)b * NQ + q0) * NN;
    const uint32_t ssBase = smem_u32(su + EXT_SS);

    float acc[4][4];
    #pragma unroll
    for (int f = 0; f < 4; f++)
        #pragma unroll
        for (int j = 0; j < 4; j++) acc[f][j] = 0.f;

    const int arow = wq * 16 + (lid >> 2);
    const int lm_km = (lid >> 3) & 1;
    const int lm_ng = lid >> 4;
    const int lm_r  = lid & 7;

    for (int n0 = nbeg; n0 < nend; n0 += 64) {
        __syncthreads();
        #pragma unroll
        for (int t = 0; t < 4; t++) {
            int idx = tid + t * 256;
            int q = idx >> 5, c = idx & 31;
            int n = n0 + 2 * c;
            float vx = 0.f, vy = 0.f;
            if (n + 1 < nend) {
                float2 v = *(const float2*)&at[(size_t)q * NN + n];
                vx = v.x; vy = v.y;
            } else if (n < nend) {
                vx = at[(size_t)q * NN + n];
            }
            su[EXT_SAT + q * 36 + c] = pack_h2(vx * ATT_SCALE, vy * ATT_SCALE);
        }
        #pragma unroll
        for (int t = 0; t < 16; t++) {
            int idx = tid + t * 256;
            int row = idx >> 6, c = idx & 63;
            int n = n0 + row;
            su[EXT_SS + row * 68 + c] =
                (n < nend) ? ((const uint32_t*)(stH + (size_t)n * ND))[c] : 0u;
        }
        __syncthreads();

        #pragma unroll
        for (int sg = 0; sg < 4; sg++) {
            const int kw = sg * 8 + (lid & 3);
            uint32_t a0 = su[EXT_SAT + arow * 36 + kw];
            uint32_t a1 = su[EXT_SAT + (arow + 8) * 36 + kw];
            uint32_t a2 = su[EXT_SAT + arow * 36 + kw + 4];
            uint32_t a3 = su[EXT_SAT + (arow + 8) * 36 + kw + 4];
            #pragma unroll
            for (int g = 0; g < 2; g++) {
                int nb = wd * 32 + g * 16;
                uint32_t addr = ssBase +
                    (uint32_t)((sg * 16 + lm_km * 8 + lm_r) * 272 +
                               (nb + lm_ng * 8) * 2);
                uint32_t r0, r1, r2, r3;
                asm volatile(
                    "ldmatrix.sync.aligned.m8n8.x4.trans.shared.b16 "
                    "{%0,%1,%2,%3}, [%4];"
                    : "=r"(r0), "=r"(r1), "=r"(r2), "=r"(r3) : "r"(addr));
                mma_f16(acc[2 * g],     a0, a1, a2, a3, r0, r1);
                mma_f16(acc[2 * g + 1], a0, a1, a2, a3, r2, r3);
            }
        }
    }

    #pragma unroll
    for (int f = 0; f < 4; f++) {
        int d = wd * 32 + f * 8 + (lid & 3) * 2;
        int q = q0 + wq * 16 + (lid >> 2);
        float* drow = out + ((size_t)(b * NQ + q)) * OUTC + NP + d;
        atomicAdd(drow,     acc[f][0] * ATT_INV);
        atomicAdd(drow + 1, acc[f][1] * ATT_INV);
        float* drow2 = out + ((size_t)(b * NQ + q + 8)) * OUTC + NP + d;
        atomicAdd(drow2,     acc[f][2] * ATT_INV);
        atomicAdd(drow2 + 1, acc[f][3] * ATT_INV);
    }
}

// =====================================================================
extern "C" void kernel_launch(void* const* d_in, const int* in_sizes, int n_in,
                              void* d_out, int out_size)
{
    const float* nodes = (const float*)d_in[0];
    const float* poses = (const float*)d_in[1];
    const float* attn  = (const float*)d_in[2];
    const int*   esrc  = (const int*)d_in[3];
    const int*   esnk  = (const int*)d_in[4];
    const float* w1e   = (const float*)d_in[5];
    const float* b1e   = (const float*)d_in[6];
    const float* w2e   = (const float*)d_in[7];
    const float* b2e   = (const float*)d_in[8];
    const float* w1n   = (const float*)d_in[9];
    const float* b1n   = (const float*)d_in[10];
    const float* w2n   = (const float*)d_in[11];
    const float* b2n   = (const float*)d_in[12];
    float* out = (float*)d_out;

    cudaFuncSetAttribute(proj_kernel, cudaFuncAttributeMaxDynamicSharedMemorySize,
                         PROJ_SMEM_BYTES);
    cudaFuncSetAttribute(edge_kernel, cudaFuncAttributeMaxDynamicSharedMemorySize,
                         EDGE_SMEM_BYTES);
    cudaFuncSetAttribute(node_kernel, cudaFuncAttributeMaxDynamicSharedMemorySize,
                         NODE_SMEM_BYTES);

    // copy + fp16 mirror + csr count zero + out init (fused)
    copy_states_kernel<<<(NB * NN * ND / 4 + 255) / 256, 256>>>(nodes, poses, out);

    // CSR chain (hist also zeroes fp16 incoming)
    csr_hist_kernel<<<(NE + 255) / 256, 256>>>(esnk);
    csr_scan_kernel<<<1, 1024>>>();
    csr_scatter_kernel<<<(NE + 255) / 256, 256>>>(esrc, esnk);
    tile_meta_kernel<<<NTE_B, TEE>>>();

    // step 0 projection from initial states; steps 1,2 fused into node
    proj_kernel<<<148, 256, PROJ_SMEM_BYTES>>>(w1e);
    for (int s = 0; s < 3; s++) {
        edge_kernel<<<148, 512, EDGE_SMEM_BYTES>>>(b1e, w2e, b2e);
        node_kernel<<<148, 256, NODE_SMEM_BYTES>>>(w1n, b1n, w2n, b2n,
                                                   w1e, (s < 2) ? 1 : 0);
    }
    extract_kernel<<<dim3(NSPLIT, NQ / 32, NB), 256, EXT_SMEM_U32 * 4>>>(attn, out);
}